// round 1
// baseline (speedup 1.0000x reference)
#include <cuda_runtime.h>

#define B_ 4
#define N_ 4096
#define F_ 1024
#define H_ 16
#define D_ 64
#define E_ 256

// Scratch (device globals: no allocation allowed in kernel_launch)
__device__ float g_q [B_*N_*F_];   // Q = x @ Wq^T           [B*N, F]
__device__ float g_xp[B_*E_*F_];   // xp = proj^T @ x        [B*E, F]
__device__ float g_kp[B_*E_*F_];   // Kp = xp @ Wk^T         [B*E, F]
__device__ float g_vp[B_*E_*F_];   // Vp = xp @ Wv^T         [B*E, F]
__device__ float g_ao[B_*N_*F_];   // attention output       [B*N, F]

// ---------------------------------------------------------------------------
// NT SGEMM: C[m,n] = sum_k A[m,k] * B[n,k]   (A row-major MxK, B row-major NxK)
// 128x128 tile, BK=8, 8x8 register tile, 256 threads, register prefetch.
// blockIdx.z selects (B0,C0) or (B1,C1) so Kp and Vp run in one launch.
// ---------------------------------------------------------------------------
__global__ void __launch_bounds__(256, 2)
sgemm_nt(const float* __restrict__ A,
         const float* __restrict__ B0, const float* __restrict__ B1,
         float* __restrict__ C0, float* __restrict__ C1,
         int M, int N, int K)
{
    const float* Bm = blockIdx.z ? B1 : B0;
    float*       C  = blockIdx.z ? C1 : C0;

    __shared__ float As[8][128];
    __shared__ float Bs[8][128];

    const int bm  = blockIdx.y * 128;
    const int bn  = blockIdx.x * 128;
    const int tid = threadIdx.x;

    // global tile loads: each thread 1 float4 of A and 1 float4 of B per k-tile
    const int ar = tid >> 1;          // 0..127 (tile row)
    const int ac = (tid & 1) * 4;     // 0 or 4 (k offset)
    const float* Ap = A  + (size_t)(bm + ar) * K + ac;
    const float* Bp = Bm + (size_t)(bn + ar) * K + ac;

    float4 a4 = *(const float4*)Ap;
    float4 b4 = *(const float4*)Bp;

    const int tx = tid & 15;          // col group (8 cols each)
    const int ty = tid >> 4;          // row group (8 rows each)

    float acc[8][8];
#pragma unroll
    for (int i = 0; i < 8; i++)
#pragma unroll
        for (int j = 0; j < 8; j++) acc[i][j] = 0.f;

    for (int kt = 0; kt < K; kt += 8) {
        // store current tile (transposed: smem is [k][m])
        As[ac + 0][ar] = a4.x; As[ac + 1][ar] = a4.y;
        As[ac + 2][ar] = a4.z; As[ac + 3][ar] = a4.w;
        Bs[ac + 0][ar] = b4.x; Bs[ac + 1][ar] = b4.y;
        Bs[ac + 2][ar] = b4.z; Bs[ac + 3][ar] = b4.w;
        __syncthreads();

        // prefetch next tile into registers while computing
        if (kt + 8 < K) {
            a4 = *(const float4*)(Ap + kt + 8);
            b4 = *(const float4*)(Bp + kt + 8);
        }

#pragma unroll
        for (int k = 0; k < 8; k++) {
            float4 A0 = *(const float4*)&As[k][ty * 8];
            float4 A1 = *(const float4*)&As[k][ty * 8 + 4];
            float4 Bx = *(const float4*)&Bs[k][tx * 8];
            float4 By = *(const float4*)&Bs[k][tx * 8 + 4];
            float av[8] = {A0.x, A0.y, A0.z, A0.w, A1.x, A1.y, A1.z, A1.w};
            float bv[8] = {Bx.x, Bx.y, Bx.z, Bx.w, By.x, By.y, By.z, By.w};
#pragma unroll
            for (int i = 0; i < 8; i++)
#pragma unroll
                for (int j = 0; j < 8; j++)
                    acc[i][j] += av[i] * bv[j];
        }
        __syncthreads();
    }

#pragma unroll
    for (int i = 0; i < 8; i++) {
        float* Cr = C + (size_t)(bm + ty * 8 + i) * N + bn + tx * 8;
        *(float4*)(Cr)     = make_float4(acc[i][0], acc[i][1], acc[i][2], acc[i][3]);
        *(float4*)(Cr + 4) = make_float4(acc[i][4], acc[i][5], acc[i][6], acc[i][7]);
    }
}

// ---------------------------------------------------------------------------
// TN GEMM: xp[b,e,f] = sum_n proj[n,e] * x[b,n,f]
// per batch: M=256(e), N=1024(f), K=4096(n). Tile 64x128, BK=16, 4x8 reg tile.
// grid = (F/128, E/64, B) = (8,4,4)
// ---------------------------------------------------------------------------
__global__ void __launch_bounds__(256)
proj_gemm(const float* __restrict__ x, const float* __restrict__ proj)
{
    __shared__ float As[16][64];    // [n_k][e]  (natural layout, e contiguous)
    __shared__ float Bs[16][128];   // [n_k][f]

    const int f0 = blockIdx.x * 128;
    const int e0 = blockIdx.y * 64;
    const int b  = blockIdx.z;
    const int tid = threadIdx.x;
    const int tx = tid & 15;        // f group (8 each)
    const int ty = tid >> 4;        // e group (4 each)

    const float* xb = x + (size_t)b * N_ * F_;

    float acc[4][8];
#pragma unroll
    for (int i = 0; i < 4; i++)
#pragma unroll
        for (int j = 0; j < 8; j++) acc[i][j] = 0.f;

    for (int n0 = 0; n0 < N_; n0 += 16) {
        {
            int r = tid >> 4, cv = tid & 15; // 16 rows x 16 float4 = 1024 floats
            *(float4*)&As[r][cv * 4] =
                *(const float4*)(proj + (size_t)(n0 + r) * E_ + e0 + cv * 4);
        }
#pragma unroll
        for (int t = 0; t < 2; t++) {
            int idx = tid + t * 256;         // 512 float4 total
            int r = idx >> 5, cv = idx & 31;
            *(float4*)&Bs[r][cv * 4] =
                *(const float4*)(xb + (size_t)(n0 + r) * F_ + f0 + cv * 4);
        }
        __syncthreads();

#pragma unroll
        for (int k = 0; k < 16; k++) {
            float4 a  = *(const float4*)&As[k][ty * 4];
            float4 bx = *(const float4*)&Bs[k][tx * 8];
            float4 by = *(const float4*)&Bs[k][tx * 8 + 4];
            float av[4] = {a.x, a.y, a.z, a.w};
            float bv[8] = {bx.x, bx.y, bx.z, bx.w, by.x, by.y, by.z, by.w};
#pragma unroll
            for (int i = 0; i < 4; i++)
#pragma unroll
                for (int j = 0; j < 8; j++)
                    acc[i][j] += av[i] * bv[j];
        }
        __syncthreads();
    }

    float* C = g_xp + (size_t)b * E_ * F_;
#pragma unroll
    for (int i = 0; i < 4; i++) {
        float* Cr = C + (size_t)(e0 + ty * 4 + i) * F_ + f0 + tx * 8;
        *(float4*)(Cr)     = make_float4(acc[i][0], acc[i][1], acc[i][2], acc[i][3]);
        *(float4*)(Cr + 4) = make_float4(acc[i][4], acc[i][5], acc[i][6], acc[i][7]);
    }
}

// ---------------------------------------------------------------------------
// Fused attention: per (b, h, 32-query tile).
// Kp/Vp tiles (256x64) resident in smem; scores + softmax fully in registers
// (warp owns 4 queries, lane owns 8 of 256 landmarks); AV via smem round-trip.
// smem: Ks[64][256] + Vs[256][64] + Qs[64][32] + Sq[32][264] = 169 KB dynamic.
// ---------------------------------------------------------------------------
#define SQ_PITCH 264

__global__ void __launch_bounds__(256)
attn_kernel()
{
    extern __shared__ float sm[];
    float* Ks = sm;                    // [d][e]  64*256
    float* Vs = Ks + 64 * E_;          // [e][d]  256*64
    float* Qs = Vs + E_ * 64;          // [d][q]  64*32
    float* Sq = Qs + 64 * 32;          // [q][e]  32*SQ_PITCH

    const int n0 = blockIdx.x * 32;
    const int h  = blockIdx.y;
    const int b  = blockIdx.z;
    const int tid  = threadIdx.x;
    const int lane = tid & 31;
    const int w    = tid >> 5;

    const float* kpb = g_kp + (size_t)b * E_ * F_ + h * D_;
    const float* vpb = g_vp + (size_t)b * E_ * F_ + h * D_;
    const float* qb  = g_q  + (size_t)b * N_ * F_ + h * D_;

    // load Kp (transposed to [d][e]) and Vp ([e][d])
    for (int idx = tid; idx < E_ * 16; idx += 256) {
        int e = idx >> 4, d4 = (idx & 15) << 2;
        float4 v = *(const float4*)(kpb + (size_t)e * F_ + d4);
        Ks[(d4 + 0) * E_ + e] = v.x;
        Ks[(d4 + 1) * E_ + e] = v.y;
        Ks[(d4 + 2) * E_ + e] = v.z;
        Ks[(d4 + 3) * E_ + e] = v.w;
        float4 u = *(const float4*)(vpb + (size_t)e * F_ + d4);
        *(float4*)(Vs + e * 64 + d4) = u;
    }
    // load Q tile transposed to [d][q], pre-scaled by 1/sqrt(D)=0.125
    for (int idx = tid; idx < 32 * 16; idx += 256) {
        int q = idx >> 4, d4 = (idx & 15) << 2;
        float4 v = *(const float4*)(qb + (size_t)(n0 + q) * F_ + d4);
        Qs[(d4 + 0) * 32 + q] = v.x * 0.125f;
        Qs[(d4 + 1) * 32 + q] = v.y * 0.125f;
        Qs[(d4 + 2) * 32 + q] = v.z * 0.125f;
        Qs[(d4 + 3) * 32 + q] = v.w * 0.125f;
    }
    __syncthreads();

    const int q0 = w * 4;   // this warp's 4 queries

    // ---- scores: c[i][j] = q[q0+i] . k[lane*8+j] ----
    float c[4][8];
#pragma unroll
    for (int i = 0; i < 4; i++)
#pragma unroll
        for (int j = 0; j < 8; j++) c[i][j] = 0.f;

#pragma unroll 4
    for (int d = 0; d < 64; d++) {
        float4 a  = *(const float4*)(Qs + d * 32 + q0);
        float4 b0 = *(const float4*)(Ks + d * E_ + lane * 8);
        float4 b1 = *(const float4*)(Ks + d * E_ + lane * 8 + 4);
        float av[4] = {a.x, a.y, a.z, a.w};
        float bv[8] = {b0.x, b0.y, b0.z, b0.w, b1.x, b1.y, b1.z, b1.w};
#pragma unroll
        for (int i = 0; i < 4; i++)
#pragma unroll
            for (int j = 0; j < 8; j++)
                c[i][j] += av[i] * bv[j];
    }

    // ---- softmax over e (distributed across 32 lanes x 8) ----
#pragma unroll
    for (int i = 0; i < 4; i++) {
        float m = c[i][0];
#pragma unroll
        for (int j = 1; j < 8; j++) m = fmaxf(m, c[i][j]);
#pragma unroll
        for (int o = 16; o > 0; o >>= 1)
            m = fmaxf(m, __shfl_xor_sync(0xffffffffu, m, o));
        float s = 0.f;
#pragma unroll
        for (int j = 0; j < 8; j++) { c[i][j] = __expf(c[i][j] - m); s += c[i][j]; }
#pragma unroll
        for (int o = 16; o > 0; o >>= 1)
            s += __shfl_xor_sync(0xffffffffu, s, o);
        float inv = 1.f / s;
#pragma unroll
        for (int j = 0; j < 8; j++) c[i][j] *= inv;
        *(float4*)(Sq + (q0 + i) * SQ_PITCH + lane * 8)     =
            make_float4(c[i][0], c[i][1], c[i][2], c[i][3]);
        *(float4*)(Sq + (q0 + i) * SQ_PITCH + lane * 8 + 4) =
            make_float4(c[i][4], c[i][5], c[i][6], c[i][7]);
    }
    __syncwarp();  // Sq rows for q0..q0+3 written/read by this warp only

    // ---- AV: out[q][d] = sum_e attn[q][e] * Vs[e][d] ; lane owns 2 d's ----
    const int d0 = lane * 2;
    float2 acc[4];
#pragma unroll
    for (int i = 0; i < 4; i++) acc[i] = make_float2(0.f, 0.f);

    for (int e = 0; e < E_; e += 4) {
        float4 aa[4];
#pragma unroll
        for (int i = 0; i < 4; i++)
            aa[i] = *(const float4*)(Sq + (q0 + i) * SQ_PITCH + e);
        float2 vv[4];
#pragma unroll
        for (int k = 0; k < 4; k++)
            vv[k] = *(const float2*)(Vs + (e + k) * 64 + d0);
#pragma unroll
        for (int i = 0; i < 4; i++) {
            float av[4] = {aa[i].x, aa[i].y, aa[i].z, aa[i].w};
#pragma unroll
            for (int k = 0; k < 4; k++) {
                acc[i].x += av[k] * vv[k].x;
                acc[i].y += av[k] * vv[k].y;
            }
        }
    }

#pragma unroll
    for (int i = 0; i < 4; i++) {
        float* p = g_ao + (size_t)(b * N_ + n0 + q0 + i) * F_ + h * D_ + d0;
        *(float2*)p = acc[i];
    }
}

// ---------------------------------------------------------------------------
extern "C" void kernel_launch(void* const* d_in, const int* in_sizes, int n_in,
                              void* d_out, int out_size)
{
    (void)in_sizes; (void)n_in; (void)out_size;
    const float* x    = (const float*)d_in[0];
    const float* proj = (const float*)d_in[1];
    const float* Wq   = (const float*)d_in[2];
    const float* Wk   = (const float*)d_in[3];
    const float* Wv   = (const float*)d_in[4];
    const float* Wo   = (const float*)d_in[5];
    float* out = (float*)d_out;

    float *pq, *pxp, *pkp, *pvp, *pao;
    cudaGetSymbolAddress((void**)&pq,  g_q);
    cudaGetSymbolAddress((void**)&pxp, g_xp);
    cudaGetSymbolAddress((void**)&pkp, g_kp);
    cudaGetSymbolAddress((void**)&pvp, g_vp);
    cudaGetSymbolAddress((void**)&pao, g_ao);

    const size_t ATT_SMEM =
        (size_t)(64 * E_ + E_ * 64 + 64 * 32 + 32 * SQ_PITCH) * sizeof(float);
    cudaFuncSetAttribute(attn_kernel,
                         cudaFuncAttributeMaxDynamicSharedMemorySize,
                         (int)ATT_SMEM);

    // 1) Q = x @ Wq^T                      [16384,1024] x [1024,1024]^T
    sgemm_nt<<<dim3(8, 128, 1), 256>>>(x, Wq, Wq, pq, pq, B_ * N_, F_, F_);
    // 2) xp = proj^T @ x  (per batch)      [256,4096]^T-reduce
    proj_gemm<<<dim3(8, 4, 4), 256>>>(x, proj);
    // 3) Kp = xp @ Wk^T ; Vp = xp @ Wv^T   (one launch via z)
    sgemm_nt<<<dim3(8, 8, 2), 256>>>(pxp, Wk, Wv, pkp, pvp, B_ * E_, F_, F_);
    // 4) fused attention -> g_ao
    attn_kernel<<<dim3(N_ / 32, H_, B_), 256, ATT_SMEM>>>();
    // 5) out = g_ao @ Wo^T
    sgemm_nt<<<dim3(8, 128, 1), 256>>>(pao, Wo, Wo, out, out, B_ * N_, F_, F_);
}

// round 2
// speedup vs baseline: 1.1579x; 1.1579x over previous
#include <cuda_runtime.h>

#define B_ 4
#define N_ 4096
#define F_ 1024
#define H_ 16
#define D_ 64
#define E_ 256
#define SPLIT 2

typedef unsigned long long ull;

// ---- packed f32x2 helpers (sm_103a native FFMA2) ----
__device__ __forceinline__ ull dup2(float v) {
    ull r; asm("mov.b64 %0, {%1, %1};" : "=l"(r) : "f"(v)); return r;
}
__device__ __forceinline__ void fma2(ull& d, ull a, ull b) {
    asm("fma.rn.f32x2 %0, %1, %2, %0;" : "+l"(d) : "l"(a), "l"(b));
}
__device__ __forceinline__ float2 upk(ull v) {
    float2 f; asm("mov.b64 {%0, %1}, %2;" : "=f"(f.x), "=f"(f.y) : "l"(v)); return f;
}

// Scratch (device globals: no allocation allowed in kernel_launch)
__device__ float g_q [B_*N_*F_];   // Q = x @ Wq^T           [B*N, F]
__device__ float g_xp[B_*E_*F_];   // xp = proj^T @ x        [B*E, F]
__device__ float g_kp[B_*E_*F_];   // Kp = xp @ Wk^T         [B*E, F]
__device__ float g_vp[B_*E_*F_];   // Vp = xp @ Wv^T         [B*E, F]
__device__ float g_ao[B_*N_*F_];   // attention output       [B*N, F]

// ---------------------------------------------------------------------------
// NT SGEMM with packed f32x2: C[m,n] = sum_k A[m,k]*B[n,k]
// 128x128 tile, BK=8, 8x8 register tile (packed as 8x4 f32x2), 256 threads.
// ---------------------------------------------------------------------------
__global__ void __launch_bounds__(256, 2)
sgemm_nt(const float* __restrict__ A,
         const float* __restrict__ B0, const float* __restrict__ B1,
         float* __restrict__ C0, float* __restrict__ C1,
         int M, int N, int K)
{
    const float* Bm = blockIdx.z ? B1 : B0;
    float*       C  = blockIdx.z ? C1 : C0;

    __shared__ float As[8][128];
    __shared__ float Bs[8][128];

    const int bm  = blockIdx.y * 128;
    const int bn  = blockIdx.x * 128;
    const int tid = threadIdx.x;

    const int ar = tid >> 1;
    const int ac = (tid & 1) * 4;
    const float* Ap = A  + (size_t)(bm + ar) * K + ac;
    const float* Bp = Bm + (size_t)(bn + ar) * K + ac;

    float4 a4 = *(const float4*)Ap;
    float4 b4 = *(const float4*)Bp;

    const int tx = tid & 15;
    const int ty = tid >> 4;

    ull acc[8][4];
#pragma unroll
    for (int i = 0; i < 8; i++)
#pragma unroll
        for (int j = 0; j < 4; j++) acc[i][j] = 0ull;

    for (int kt = 0; kt < K; kt += 8) {
        As[ac + 0][ar] = a4.x; As[ac + 1][ar] = a4.y;
        As[ac + 2][ar] = a4.z; As[ac + 3][ar] = a4.w;
        Bs[ac + 0][ar] = b4.x; Bs[ac + 1][ar] = b4.y;
        Bs[ac + 2][ar] = b4.z; Bs[ac + 3][ar] = b4.w;
        __syncthreads();

        if (kt + 8 < K) {
            a4 = *(const float4*)(Ap + kt + 8);
            b4 = *(const float4*)(Bp + kt + 8);
        }

#pragma unroll
        for (int k = 0; k < 8; k++) {
            float4 A0 = *(const float4*)&As[k][ty * 8];
            float4 A1 = *(const float4*)&As[k][ty * 8 + 4];
            ulonglong2 bb0 = *(const ulonglong2*)&Bs[k][tx * 8];
            ulonglong2 bb1 = *(const ulonglong2*)&Bs[k][tx * 8 + 4];
            float av[8] = {A0.x, A0.y, A0.z, A0.w, A1.x, A1.y, A1.z, A1.w};
#pragma unroll
            for (int i = 0; i < 8; i++) {
                ull ad = dup2(av[i]);
                fma2(acc[i][0], ad, bb0.x);
                fma2(acc[i][1], ad, bb0.y);
                fma2(acc[i][2], ad, bb1.x);
                fma2(acc[i][3], ad, bb1.y);
            }
        }
        __syncthreads();
    }

#pragma unroll
    for (int i = 0; i < 8; i++) {
        float2 p0 = upk(acc[i][0]), p1 = upk(acc[i][1]);
        float2 p2 = upk(acc[i][2]), p3 = upk(acc[i][3]);
        float* Cr = C + (size_t)(bm + ty * 8 + i) * N + bn + tx * 8;
        *(float4*)(Cr)     = make_float4(p0.x, p0.y, p1.x, p1.y);
        *(float4*)(Cr + 4) = make_float4(p2.x, p2.y, p3.x, p3.y);
    }
}

// ---------------------------------------------------------------------------
// TN GEMM: xp[b,e,f] = sum_n proj[n,e] * x[b,n,f]   (packed f32x2)
// ---------------------------------------------------------------------------
__global__ void __launch_bounds__(256)
proj_gemm(const float* __restrict__ x, const float* __restrict__ proj)
{
    __shared__ float As[16][64];
    __shared__ float Bs[16][128];

    const int f0 = blockIdx.x * 128;
    const int e0 = blockIdx.y * 64;
    const int b  = blockIdx.z;
    const int tid = threadIdx.x;
    const int tx = tid & 15;
    const int ty = tid >> 4;

    const float* xb = x + (size_t)b * N_ * F_;

    ull acc[4][4];
#pragma unroll
    for (int i = 0; i < 4; i++)
#pragma unroll
        for (int j = 0; j < 4; j++) acc[i][j] = 0ull;

    for (int n0 = 0; n0 < N_; n0 += 16) {
        {
            int r = tid >> 4, cv = tid & 15;
            *(float4*)&As[r][cv * 4] =
                *(const float4*)(proj + (size_t)(n0 + r) * E_ + e0 + cv * 4);
        }
#pragma unroll
        for (int t = 0; t < 2; t++) {
            int idx = tid + t * 256;
            int r = idx >> 5, cv = idx & 31;
            *(float4*)&Bs[r][cv * 4] =
                *(const float4*)(xb + (size_t)(n0 + r) * F_ + f0 + cv * 4);
        }
        __syncthreads();

#pragma unroll
        for (int k = 0; k < 16; k++) {
            float4 a = *(const float4*)&As[k][ty * 4];
            ulonglong2 bb0 = *(const ulonglong2*)&Bs[k][tx * 8];
            ulonglong2 bb1 = *(const ulonglong2*)&Bs[k][tx * 8 + 4];
            float av[4] = {a.x, a.y, a.z, a.w};
#pragma unroll
            for (int i = 0; i < 4; i++) {
                ull ad = dup2(av[i]);
                fma2(acc[i][0], ad, bb0.x);
                fma2(acc[i][1], ad, bb0.y);
                fma2(acc[i][2], ad, bb1.x);
                fma2(acc[i][3], ad, bb1.y);
            }
        }
        __syncthreads();
    }

    float* Cb = g_xp + (size_t)b * E_ * F_;
#pragma unroll
    for (int i = 0; i < 4; i++) {
        float2 p0 = upk(acc[i][0]), p1 = upk(acc[i][1]);
        float2 p2 = upk(acc[i][2]), p3 = upk(acc[i][3]);
        float* Cr = Cb + (size_t)(e0 + ty * 4 + i) * F_ + f0 + tx * 8;
        *(float4*)(Cr)     = make_float4(p0.x, p0.y, p1.x, p1.y);
        *(float4*)(Cr + 4) = make_float4(p2.x, p2.y, p3.x, p3.y);
    }
}

// ---------------------------------------------------------------------------
// Persistent fused attention. grid = (SPLIT, H, B) = 128 CTAs.
// Each CTA: load K[64][256] + V[256][64] once, then loop over query tiles.
// Each warp owns 8 queries; warp-private Q/score smem -> only __syncwarp in
// the mainloop. Packed f32x2 everywhere. smem = 208KB.
// ---------------------------------------------------------------------------
__global__ void __launch_bounds__(256, 1)
attn_kernel()
{
    extern __shared__ float sm[];
    float* Ks = sm;                    // [d][e]   64*256
    float* Vs = Ks + 64 * E_;          // [e][d]   256*64
    float* Qw = Vs + E_ * 64;          // [warp][8][64]
    float* Sw = Qw + 8 * 8 * 64;       // [warp][8][256]

    const int h  = blockIdx.y;
    const int b  = blockIdx.z;
    const int tid  = threadIdx.x;
    const int lane = tid & 31;
    const int w    = tid >> 5;

    const float* kpb = g_kp + (size_t)b * E_ * F_ + h * D_;
    const float* vpb = g_vp + (size_t)b * E_ * F_ + h * D_;

    // load Kp (transposed to [d][e]) and Vp ([e][d]) cooperatively, once
    for (int idx = tid; idx < E_ * 16; idx += 256) {
        int e = idx >> 4, d4 = (idx & 15) << 2;
        float4 v = *(const float4*)(kpb + (size_t)e * F_ + d4);
        Ks[(d4 + 0) * E_ + e] = v.x;
        Ks[(d4 + 1) * E_ + e] = v.y;
        Ks[(d4 + 2) * E_ + e] = v.z;
        Ks[(d4 + 3) * E_ + e] = v.w;
        float4 u = *(const float4*)(vpb + (size_t)e * F_ + d4);
        *(float4*)(Vs + e * 64 + d4) = u;
    }
    __syncthreads();

    float* Qm = Qw + w * 8 * 64;
    float* Sm = Sw + w * 8 * 256;
    const int d0 = lane * 2;

    for (int t = blockIdx.x; t < N_ / 64; t += SPLIT) {
        const int n0 = t * 64 + w * 8;            // this warp's 8 query rows
        const float* qp = g_q + (size_t)(b * N_ + n0) * F_ + h * D_;

        // load 8x64 Q rows (pre-scaled by 1/sqrt(D) = 0.125)
#pragma unroll
        for (int s = 0; s < 4; s++) {
            int idx = s * 32 + lane;
            int r = idx >> 4, c = (idx & 15) * 4;
            float4 v = *(const float4*)(qp + (size_t)r * F_ + c);
            *(float4*)(Qm + r * 64 + c) =
                make_float4(v.x * 0.125f, v.y * 0.125f, v.z * 0.125f, v.w * 0.125f);
        }
        __syncwarp();

        // ---- scores ----
        ull c2[8][4];
#pragma unroll
        for (int i = 0; i < 8; i++)
#pragma unroll
            for (int jp = 0; jp < 4; jp++) c2[i][jp] = 0ull;

        for (int dc = 0; dc < 64; dc += 4) {
            ull kb[4][4];
#pragma unroll
            for (int dd = 0; dd < 4; dd++) {
                ulonglong2 t0 = *(const ulonglong2*)&Ks[(dc + dd) * E_ + lane * 8];
                ulonglong2 t1 = *(const ulonglong2*)&Ks[(dc + dd) * E_ + lane * 8 + 4];
                kb[dd][0] = t0.x; kb[dd][1] = t0.y;
                kb[dd][2] = t1.x; kb[dd][3] = t1.y;
            }
#pragma unroll
            for (int i = 0; i < 8; i++) {
                float4 q = *(const float4*)&Qm[i * 64 + dc];
                float qa[4] = {q.x, q.y, q.z, q.w};
#pragma unroll
                for (int dd = 0; dd < 4; dd++) {
                    ull qd = dup2(qa[dd]);
                    fma2(c2[i][0], qd, kb[dd][0]);
                    fma2(c2[i][1], qd, kb[dd][1]);
                    fma2(c2[i][2], qd, kb[dd][2]);
                    fma2(c2[i][3], qd, kb[dd][3]);
                }
            }
        }

        // ---- softmax per query row (8 vals/lane over 256 e) ----
#pragma unroll
        for (int i = 0; i < 8; i++) {
            float2 v0 = upk(c2[i][0]), v1 = upk(c2[i][1]);
            float2 v2 = upk(c2[i][2]), v3 = upk(c2[i][3]);
            float va[8] = {v0.x, v0.y, v1.x, v1.y, v2.x, v2.y, v3.x, v3.y};
            float m = va[0];
#pragma unroll
            for (int j = 1; j < 8; j++) m = fmaxf(m, va[j]);
#pragma unroll
            for (int o = 16; o > 0; o >>= 1)
                m = fmaxf(m, __shfl_xor_sync(0xffffffffu, m, o));
            float s = 0.f;
#pragma unroll
            for (int j = 0; j < 8; j++) { va[j] = __expf(va[j] - m); s += va[j]; }
#pragma unroll
            for (int o = 16; o > 0; o >>= 1)
                s += __shfl_xor_sync(0xffffffffu, s, o);
            float inv = 1.f / s;
#pragma unroll
            for (int j = 0; j < 8; j++) va[j] *= inv;
            *(float4*)&Sm[i * E_ + lane * 8] =
                make_float4(va[0], va[1], va[2], va[3]);
            *(float4*)&Sm[i * E_ + lane * 8 + 4] =
                make_float4(va[4], va[5], va[6], va[7]);
        }
        __syncwarp();

        // ---- AV ----
        ull acc[8];
#pragma unroll
        for (int i = 0; i < 8; i++) acc[i] = 0ull;

        for (int e = 0; e < E_; e += 4) {
            ull vv[4];
#pragma unroll
            for (int k4 = 0; k4 < 4; k4++)
                vv[k4] = *(const ull*)&Vs[(e + k4) * 64 + d0];
#pragma unroll
            for (int i = 0; i < 8; i++) {
                float4 aa = *(const float4*)&Sm[i * E_ + e];
                fma2(acc[i], dup2(aa.x), vv[0]);
                fma2(acc[i], dup2(aa.y), vv[1]);
                fma2(acc[i], dup2(aa.z), vv[2]);
                fma2(acc[i], dup2(aa.w), vv[3]);
            }
        }

        float* aop = g_ao + (size_t)(b * N_ + n0) * F_ + h * D_ + d0;
#pragma unroll
        for (int i = 0; i < 8; i++) {
            float2 o = upk(acc[i]);
            *(float2*)(aop + (size_t)i * F_) = o;
        }
    }
}

// ---------------------------------------------------------------------------
extern "C" void kernel_launch(void* const* d_in, const int* in_sizes, int n_in,
                              void* d_out, int out_size)
{
    (void)in_sizes; (void)n_in; (void)out_size;
    const float* x    = (const float*)d_in[0];
    const float* proj = (const float*)d_in[1];
    const float* Wq   = (const float*)d_in[2];
    const float* Wk   = (const float*)d_in[3];
    const float* Wv   = (const float*)d_in[4];
    const float* Wo   = (const float*)d_in[5];
    float* out = (float*)d_out;

    float *pq, *pxp, *pkp, *pvp, *pao;
    cudaGetSymbolAddress((void**)&pq,  g_q);
    cudaGetSymbolAddress((void**)&pxp, g_xp);
    cudaGetSymbolAddress((void**)&pkp, g_kp);
    cudaGetSymbolAddress((void**)&pvp, g_vp);
    cudaGetSymbolAddress((void**)&pao, g_ao);

    const size_t ATT_SMEM =
        (size_t)(64 * E_ + E_ * 64 + 8 * 8 * 64 + 8 * 8 * E_) * sizeof(float);
    cudaFuncSetAttribute(attn_kernel,
                         cudaFuncAttributeMaxDynamicSharedMemorySize,
                         (int)ATT_SMEM);

    // 1) xp = proj^T @ x  (per batch)
    proj_gemm<<<dim3(8, 4, 4), 256>>>(x, proj);
    // 2) Kp = xp @ Wk^T ; Vp = xp @ Wv^T
    sgemm_nt<<<dim3(8, 8, 2), 256>>>(pxp, Wk, Wv, pkp, pvp, B_ * E_, F_, F_);
    // 3) Q = x @ Wq^T
    sgemm_nt<<<dim3(8, 128, 1), 256>>>(x, Wq, Wq, pq, pq, B_ * N_, F_, F_);
    // 4) fused persistent attention -> g_ao
    attn_kernel<<<dim3(SPLIT, H_, B_), 256, ATT_SMEM>>>();
    // 5) out = g_ao @ Wo^T
    sgemm_nt<<<dim3(8, 128, 1), 256>>>(pao, Wo, Wo, out, out, B_ * N_, F_, F_);
}

// round 3
// speedup vs baseline: 1.3985x; 1.2078x over previous
#include <cuda_runtime.h>

#define B_ 4
#define N_ 4096
#define F_ 1024
#define H_ 16
#define D_ 64
#define E_ 256
#define SPLIT 2

typedef unsigned long long ull;

// ---- packed f32x2 helpers (sm_103a native FFMA2) ----
__device__ __forceinline__ ull dup2(float v) {
    ull r; asm("mov.b64 %0, {%1, %1};" : "=l"(r) : "f"(v)); return r;
}
__device__ __forceinline__ void fma2(ull& d, ull a, ull b) {
    asm("fma.rn.f32x2 %0, %1, %2, %0;" : "+l"(d) : "l"(a), "l"(b));
}
__device__ __forceinline__ float2 upk(ull v) {
    float2 f; asm("mov.b64 {%0, %1}, %2;" : "=f"(f.x), "=f"(f.y) : "l"(v)); return f;
}

// Scratch (device globals)
__device__ float g_q [B_*N_*F_];
__device__ float g_xp[B_*E_*F_];
__device__ float g_kp[B_*E_*F_];
__device__ float g_vp[B_*E_*F_];
__device__ float g_ao[B_*N_*F_];

// ---------------------------------------------------------------------------
// NT SGEMM, packed f32x2, conflict-free fragment mapping.
// 128x128 tile, BK=8, 256 thr. Warp tile 32x64; thread tile 8 rows x (4+4) cols.
// ---------------------------------------------------------------------------
__global__ void __launch_bounds__(256, 2)
sgemm_nt(const float* __restrict__ A,
         const float* __restrict__ B0, const float* __restrict__ B1,
         float* __restrict__ C0, float* __restrict__ C1,
         int M, int N, int K)
{
    const float* Bm = blockIdx.z ? B1 : B0;
    float*       C  = blockIdx.z ? C1 : C0;

    __shared__ float As[8][128];
    __shared__ float Bs[8][128];

    const int bm  = blockIdx.y * 128;
    const int bn  = blockIdx.x * 128;
    const int tid = threadIdx.x;
    const int lane = tid & 31;
    const int w    = tid >> 5;

    const int ar = tid >> 1;
    const int ac = (tid & 1) * 4;
    const float* Ap = A  + (size_t)(bm + ar) * K + ac;
    const float* Bp = Bm + (size_t)(bn + ar) * K + ac;

    float4 a4 = *(const float4*)Ap;
    float4 b4 = *(const float4*)Bp;

    // conflict-free ownership
    const int r0 = (w & 3) * 32 + (lane >> 3) * 8;   // 8 rows
    const int ca = (w >> 2) * 64 + (lane & 7) * 4;   // cols ca..ca+3
    const int cb = ca + 32;                           // cols cb..cb+3

    ull acc[8][4];
#pragma unroll
    for (int i = 0; i < 8; i++)
#pragma unroll
        for (int j = 0; j < 4; j++) acc[i][j] = 0ull;

    for (int kt = 0; kt < K; kt += 8) {
        As[ac + 0][ar] = a4.x; As[ac + 1][ar] = a4.y;
        As[ac + 2][ar] = a4.z; As[ac + 3][ar] = a4.w;
        Bs[ac + 0][ar] = b4.x; Bs[ac + 1][ar] = b4.y;
        Bs[ac + 2][ar] = b4.z; Bs[ac + 3][ar] = b4.w;
        __syncthreads();

        if (kt + 8 < K) {
            a4 = *(const float4*)(Ap + kt + 8);
            b4 = *(const float4*)(Bp + kt + 8);
        }

#pragma unroll
        for (int k = 0; k < 8; k++) {
            float4 A0 = *(const float4*)&As[k][r0];
            float4 A1 = *(const float4*)&As[k][r0 + 4];
            ulonglong2 bb0 = *(const ulonglong2*)&Bs[k][ca];
            ulonglong2 bb1 = *(const ulonglong2*)&Bs[k][cb];
            float av[8] = {A0.x, A0.y, A0.z, A0.w, A1.x, A1.y, A1.z, A1.w};
#pragma unroll
            for (int i = 0; i < 8; i++) {
                ull ad = dup2(av[i]);
                fma2(acc[i][0], ad, bb0.x);
                fma2(acc[i][1], ad, bb0.y);
                fma2(acc[i][2], ad, bb1.x);
                fma2(acc[i][3], ad, bb1.y);
            }
        }
        __syncthreads();
    }

#pragma unroll
    for (int i = 0; i < 8; i++) {
        float2 p0 = upk(acc[i][0]), p1 = upk(acc[i][1]);
        float2 p2 = upk(acc[i][2]), p3 = upk(acc[i][3]);
        float* Cr = C + (size_t)(bm + r0 + i) * N + bn;
        *(float4*)(Cr + ca) = make_float4(p0.x, p0.y, p1.x, p1.y);
        *(float4*)(Cr + cb) = make_float4(p2.x, p2.y, p3.x, p3.y);
    }
}

// ---------------------------------------------------------------------------
// TN GEMM: xp[b,e,f] = sum_n proj[n,e] * x[b,n,f]
// Tile 64(e)x128(f), BK=16. Warp tile 16x64; thread 4 rows x (4+4) cols.
// ---------------------------------------------------------------------------
__global__ void __launch_bounds__(256)
proj_gemm(const float* __restrict__ x, const float* __restrict__ proj)
{
    __shared__ float As[16][64];
    __shared__ float Bs[16][128];

    const int f0 = blockIdx.x * 128;
    const int e0 = blockIdx.y * 64;
    const int b  = blockIdx.z;
    const int tid = threadIdx.x;
    const int lane = tid & 31;
    const int w    = tid >> 5;

    const int r0 = (w & 3) * 16 + (lane >> 3) * 4;   // 4 e-rows
    const int ca = (w >> 2) * 64 + (lane & 7) * 4;
    const int cb = ca + 32;

    const float* xb = x + (size_t)b * N_ * F_;

    ull acc[4][4];
#pragma unroll
    for (int i = 0; i < 4; i++)
#pragma unroll
        for (int j = 0; j < 4; j++) acc[i][j] = 0ull;

    for (int n0 = 0; n0 < N_; n0 += 16) {
        {
            int r = tid >> 4, cv = tid & 15;
            *(float4*)&As[r][cv * 4] =
                *(const float4*)(proj + (size_t)(n0 + r) * E_ + e0 + cv * 4);
        }
#pragma unroll
        for (int t = 0; t < 2; t++) {
            int idx = tid + t * 256;
            int r = idx >> 5, cv = idx & 31;
            *(float4*)&Bs[r][cv * 4] =
                *(const float4*)(xb + (size_t)(n0 + r) * F_ + f0 + cv * 4);
        }
        __syncthreads();

#pragma unroll
        for (int k = 0; k < 16; k++) {
            float4 a = *(const float4*)&As[k][r0];
            ulonglong2 bb0 = *(const ulonglong2*)&Bs[k][ca];
            ulonglong2 bb1 = *(const ulonglong2*)&Bs[k][cb];
            float av[4] = {a.x, a.y, a.z, a.w};
#pragma unroll
            for (int i = 0; i < 4; i++) {
                ull ad = dup2(av[i]);
                fma2(acc[i][0], ad, bb0.x);
                fma2(acc[i][1], ad, bb0.y);
                fma2(acc[i][2], ad, bb1.x);
                fma2(acc[i][3], ad, bb1.y);
            }
        }
        __syncthreads();
    }

    float* Cb = g_xp + (size_t)b * E_ * F_;
#pragma unroll
    for (int i = 0; i < 4; i++) {
        float2 p0 = upk(acc[i][0]), p1 = upk(acc[i][1]);
        float2 p2 = upk(acc[i][2]), p3 = upk(acc[i][3]);
        float* Cr = Cb + (size_t)(e0 + r0 + i) * F_ + f0;
        *(float4*)(Cr + ca) = make_float4(p0.x, p0.y, p1.x, p1.y);
        *(float4*)(Cr + cb) = make_float4(p2.x, p2.y, p3.x, p3.y);
    }
}

// ---------------------------------------------------------------------------
// Persistent fused attention. grid (SPLIT,H,B)=128 CTAs, 256 thr, smem 208KB.
// Lane owns e in {lane*4..+3} U {128+lane*4..+3}  -> conflict-free K loads.
// ---------------------------------------------------------------------------
__global__ void __launch_bounds__(256, 1)
attn_kernel()
{
    extern __shared__ float sm[];
    float* Ks = sm;                    // [d][e]   64*256
    float* Vs = Ks + 64 * E_;          // [e][d]   256*64
    float* Qw = Vs + E_ * 64;          // [warp][8][64]
    float* Sw = Qw + 8 * 8 * 64;       // [warp][8][256]

    const int h  = blockIdx.y;
    const int b  = blockIdx.z;
    const int tid  = threadIdx.x;
    const int lane = tid & 31;
    const int w    = tid >> 5;

    const float* kpb = g_kp + (size_t)b * E_ * F_ + h * D_;
    const float* vpb = g_vp + (size_t)b * E_ * F_ + h * D_;

    for (int idx = tid; idx < E_ * 16; idx += 256) {
        int e = idx >> 4, d4 = (idx & 15) << 2;
        float4 v = *(const float4*)(kpb + (size_t)e * F_ + d4);
        Ks[(d4 + 0) * E_ + e] = v.x;
        Ks[(d4 + 1) * E_ + e] = v.y;
        Ks[(d4 + 2) * E_ + e] = v.z;
        Ks[(d4 + 3) * E_ + e] = v.w;
        float4 u = *(const float4*)(vpb + (size_t)e * F_ + d4);
        *(float4*)(Vs + e * 64 + d4) = u;
    }
    __syncthreads();

    float* Qm = Qw + w * 8 * 64;
    float* Sm = Sw + w * 8 * 256;
    const int d0 = lane * 2;
    const int ea = lane * 4;          // e block A
    const int eb = 128 + lane * 4;    // e block B

    for (int t = blockIdx.x; t < N_ / 64; t += SPLIT) {
        const int n0 = t * 64 + w * 8;
        const float* qp = g_q + (size_t)(b * N_ + n0) * F_ + h * D_;

#pragma unroll
        for (int s = 0; s < 4; s++) {
            int idx = s * 32 + lane;
            int r = idx >> 4, c = (idx & 15) * 4;
            float4 v = *(const float4*)(qp + (size_t)r * F_ + c);
            *(float4*)(Qm + r * 64 + c) =
                make_float4(v.x * 0.125f, v.y * 0.125f, v.z * 0.125f, v.w * 0.125f);
        }
        __syncwarp();

        // ---- scores: acc pairs [0,1]=ea+{0,1},{2,3}; [2,3]=eb ----
        ull c2[8][4];
#pragma unroll
        for (int i = 0; i < 8; i++)
#pragma unroll
            for (int jp = 0; jp < 4; jp++) c2[i][jp] = 0ull;

        for (int dc = 0; dc < 64; dc += 4) {
            ull ka[4][2], kb[4][2];
#pragma unroll
            for (int dd = 0; dd < 4; dd++) {
                ulonglong2 t0 = *(const ulonglong2*)&Ks[(dc + dd) * E_ + ea];
                ulonglong2 t1 = *(const ulonglong2*)&Ks[(dc + dd) * E_ + eb];
                ka[dd][0] = t0.x; ka[dd][1] = t0.y;
                kb[dd][0] = t1.x; kb[dd][1] = t1.y;
            }
#pragma unroll
            for (int i = 0; i < 8; i++) {
                float4 q = *(const float4*)&Qm[i * 64 + dc];
                float qa[4] = {q.x, q.y, q.z, q.w};
#pragma unroll
                for (int dd = 0; dd < 4; dd++) {
                    ull qd = dup2(qa[dd]);
                    fma2(c2[i][0], qd, ka[dd][0]);
                    fma2(c2[i][1], qd, ka[dd][1]);
                    fma2(c2[i][2], qd, kb[dd][0]);
                    fma2(c2[i][3], qd, kb[dd][1]);
                }
            }
        }

        // ---- softmax per query row ----
#pragma unroll
        for (int i = 0; i < 8; i++) {
            float2 v0 = upk(c2[i][0]), v1 = upk(c2[i][1]);
            float2 v2 = upk(c2[i][2]), v3 = upk(c2[i][3]);
            float va[8] = {v0.x, v0.y, v1.x, v1.y, v2.x, v2.y, v3.x, v3.y};
            float m = va[0];
#pragma unroll
            for (int j = 1; j < 8; j++) m = fmaxf(m, va[j]);
#pragma unroll
            for (int o = 16; o > 0; o >>= 1)
                m = fmaxf(m, __shfl_xor_sync(0xffffffffu, m, o));
            float s = 0.f;
#pragma unroll
            for (int j = 0; j < 8; j++) { va[j] = __expf(va[j] - m); s += va[j]; }
#pragma unroll
            for (int o = 16; o > 0; o >>= 1)
                s += __shfl_xor_sync(0xffffffffu, s, o);
            float inv = 1.f / s;
#pragma unroll
            for (int j = 0; j < 8; j++) va[j] *= inv;
            *(float4*)&Sm[i * E_ + ea] = make_float4(va[0], va[1], va[2], va[3]);
            *(float4*)&Sm[i * E_ + eb] = make_float4(va[4], va[5], va[6], va[7]);
        }
        __syncwarp();

        // ---- AV: out[q][d0,d0+1] = sum_e w(q,e) * V[e][d0,d0+1] ----
        ull acc[8];
#pragma unroll
        for (int i = 0; i < 8; i++) acc[i] = 0ull;

        for (int e = 0; e < E_; e += 4) {
            ull vv[4];
#pragma unroll
            for (int k4 = 0; k4 < 4; k4++)
                vv[k4] = *(const ull*)&Vs[(e + k4) * 64 + d0];
#pragma unroll
            for (int i = 0; i < 8; i++) {
                float4 aa = *(const float4*)&Sm[i * E_ + e];
                fma2(acc[i], dup2(aa.x), vv[0]);
                fma2(acc[i], dup2(aa.y), vv[1]);
                fma2(acc[i], dup2(aa.z), vv[2]);
                fma2(acc[i], dup2(aa.w), vv[3]);
            }
        }

        float* aop = g_ao + (size_t)(b * N_ + n0) * F_ + h * D_ + d0;
#pragma unroll
        for (int i = 0; i < 8; i++) {
            float2 o = upk(acc[i]);
            *(float2*)(aop + (size_t)i * F_) = o;
        }
    }
}

// ---------------------------------------------------------------------------
extern "C" void kernel_launch(void* const* d_in, const int* in_sizes, int n_in,
                              void* d_out, int out_size)
{
    (void)in_sizes; (void)n_in; (void)out_size;
    const float* x    = (const float*)d_in[0];
    const float* proj = (const float*)d_in[1];
    const float* Wq   = (const float*)d_in[2];
    const float* Wk   = (const float*)d_in[3];
    const float* Wv   = (const float*)d_in[4];
    const float* Wo   = (const float*)d_in[5];
    float* out = (float*)d_out;

    float *pq, *pxp, *pkp, *pvp, *pao;
    cudaGetSymbolAddress((void**)&pq,  g_q);
    cudaGetSymbolAddress((void**)&pxp, g_xp);
    cudaGetSymbolAddress((void**)&pkp, g_kp);
    cudaGetSymbolAddress((void**)&pvp, g_vp);
    cudaGetSymbolAddress((void**)&pao, g_ao);

    const size_t ATT_SMEM =
        (size_t)(64 * E_ + E_ * 64 + 8 * 8 * 64 + 8 * 8 * E_) * sizeof(float);
    cudaFuncSetAttribute(attn_kernel,
                         cudaFuncAttributeMaxDynamicSharedMemorySize,
                         (int)ATT_SMEM);

    // 1) xp = proj^T @ x  (per batch)
    proj_gemm<<<dim3(8, 4, 4), 256>>>(x, proj);
    // 2) Kp = xp @ Wk^T ; Vp = xp @ Wv^T
    sgemm_nt<<<dim3(8, 8, 2), 256>>>(pxp, Wk, Wv, pkp, pvp, B_ * E_, F_, F_);
    // 3) Q = x @ Wq^T
    sgemm_nt<<<dim3(8, 128, 1), 256>>>(x, Wq, Wq, pq, pq, B_ * N_, F_, F_);
    // 4) fused persistent attention -> g_ao
    attn_kernel<<<dim3(SPLIT, H_, B_), 256, ATT_SMEM>>>();
    // 5) out = g_ao @ Wo^T
    sgemm_nt<<<dim3(8, 128, 1), 256>>>(pao, Wo, Wo, out, out, B_ * N_, F_, F_);
}

// round 5
// speedup vs baseline: 1.9416x; 1.3883x over previous
#include <cuda_runtime.h>
#include <cuda_bf16.h>
#include <cstdint>

#define B_ 4
#define N_ 4096
#define F_ 1024
#define H_ 16
#define D_ 64
#define E_ 256
#define SPLIT 2

typedef unsigned long long ull;

// ---- packed f32x2 helpers (sm_103a native FFMA2) ----
__device__ __forceinline__ ull dup2(float v) {
    ull r; asm("mov.b64 %0, {%1, %1};" : "=l"(r) : "f"(v)); return r;
}
__device__ __forceinline__ void fma2(ull& d, ull a, ull b) {
    asm("fma.rn.f32x2 %0, %1, %2, %0;" : "+l"(d) : "l"(a), "l"(b));
}
__device__ __forceinline__ float2 upk(ull v) {
    float2 f; asm("mov.b64 {%0, %1}, %2;" : "=f"(f.x), "=f"(f.y) : "l"(v)); return f;
}

// ---- portable tensor-core helpers (sm_80+ PTX, no arch-gated features) ----
__device__ __forceinline__ uint32_t smem_u32(const void* p) {
    uint32_t a;
    asm("{ .reg .u64 t; cvta.to.shared.u64 t, %1; cvt.u32.u64 %0, t; }" : "=r"(a) : "l"(p));
    return a;
}
__device__ __forceinline__ void ldsm4(uint32_t* r, uint32_t a) {
    asm volatile("ldmatrix.sync.aligned.m8n8.x4.shared.b16 {%0,%1,%2,%3}, [%4];"
        : "=r"(r[0]), "=r"(r[1]), "=r"(r[2]), "=r"(r[3]) : "r"(a));
}
__device__ __forceinline__ void mma16816(float* c, const uint32_t* a, const uint32_t* b) {
    asm volatile("mma.sync.aligned.m16n8k16.row.col.f32.bf16.bf16.f32 "
        "{%0,%1,%2,%3}, {%4,%5,%6,%7}, {%8,%9}, {%0,%1,%2,%3};"
        : "+f"(c[0]), "+f"(c[1]), "+f"(c[2]), "+f"(c[3])
        : "r"(a[0]), "r"(a[1]), "r"(a[2]), "r"(a[3]), "r"(b[0]), "r"(b[1]));
}
#define CP16(dst, src) asm volatile("cp.async.cg.shared.global [%0], [%1], 16;" :: "r"(dst), "l"(src))
#define CP_COMMIT()    asm volatile("cp.async.commit_group;" ::: "memory")
#define CP_WAIT1()     asm volatile("cp.async.wait_group 1;" ::: "memory")
#define CP_WAIT0()     asm volatile("cp.async.wait_group 0;" ::: "memory")

// ---- scratch (device globals) ----
__device__ float g_q [B_*N_*F_];
__device__ float g_xp[B_*E_*F_];
__device__ float g_kp[B_*E_*F_];
__device__ float g_vp[B_*E_*F_];
__device__ __nv_bfloat16 g_xh [B_*N_*F_], g_xl [B_*N_*F_];
__device__ __nv_bfloat16 g_aoh[B_*N_*F_], g_aol[B_*N_*F_];
__device__ __nv_bfloat16 g_wqh[F_*F_], g_wql[F_*F_];
__device__ __nv_bfloat16 g_woh[F_*F_], g_wol[F_*F_];

// ---------------------------------------------------------------------------
// split fp32 -> (hi, lo) bf16
// ---------------------------------------------------------------------------
__global__ void __launch_bounds__(256)
split_bf16(const float* __restrict__ in, __nv_bfloat16* __restrict__ hi,
           __nv_bfloat16* __restrict__ lo, int n4)
{
    int i = blockIdx.x * 256 + threadIdx.x;
    if (i >= n4) return;
    float4 v = ((const float4*)in)[i];
    __nv_bfloat16 h0 = __float2bfloat16(v.x), h1 = __float2bfloat16(v.y);
    __nv_bfloat16 h2 = __float2bfloat16(v.z), h3 = __float2bfloat16(v.w);
    __nv_bfloat16 l0 = __float2bfloat16(v.x - __bfloat162float(h0));
    __nv_bfloat16 l1 = __float2bfloat16(v.y - __bfloat162float(h1));
    __nv_bfloat16 l2 = __float2bfloat16(v.z - __bfloat162float(h2));
    __nv_bfloat16 l3 = __float2bfloat16(v.w - __bfloat162float(h3));
    ((__nv_bfloat162*)hi)[i*2]   = __nv_bfloat162(h0, h1);
    ((__nv_bfloat162*)hi)[i*2+1] = __nv_bfloat162(h2, h3);
    ((__nv_bfloat162*)lo)[i*2]   = __nv_bfloat162(l0, l1);
    ((__nv_bfloat162*)lo)[i*2+1] = __nv_bfloat162(l2, l3);
}

// ---------------------------------------------------------------------------
// Tensor-core split-bf16 NT GEMM via mma.sync.m16n8k16 (portable HMMA path).
// C[m,n] = sum_k A[m,k]*B[n,k], K = N = 1024.
// CTA tile 128x128, BK=32, 8 warps (warp tile 64x32 = 4x4 m16n8 tiles).
// PAD=40 bf16 rows: conflict-free ldmatrix phases. Double-buffered cp.async.
// ---------------------------------------------------------------------------
#define PAD        40
#define MAT_BYTES  (128 * PAD * 2)        // 10240 B per matrix tile
#define STG_BYTES  (4 * MAT_BYTES)        // 40960 B per stage
#define TCG_SMEM   (2 * STG_BYTES)        // 81920 B

__device__ __forceinline__ void stage_load(
    const __nv_bfloat16* __restrict__ Ah, const __nv_bfloat16* __restrict__ Al,
    const __nv_bfloat16* __restrict__ Bh, const __nv_bfloat16* __restrict__ Bl,
    int bm, int bn, int kt, uint32_t sbase, int tid)
{
    const __nv_bfloat16* gp[4] = {
        Ah + (size_t)bm * 1024, Al + (size_t)bm * 1024,
        Bh + (size_t)bn * 1024, Bl + (size_t)bn * 1024 };
#pragma unroll
    for (int m = 0; m < 4; m++) {
        const __nv_bfloat16* base = gp[m] + kt * 32;
        uint32_t sb = sbase + m * MAT_BYTES;
#pragma unroll
        for (int it = 0; it < 2; it++) {
            int c = tid + it * 256;
            int row = c >> 2, q = c & 3;
            CP16(sb + row * (PAD * 2) + q * 16, base + (size_t)row * 1024 + q * 8);
        }
    }
}

__global__ void __launch_bounds__(256, 1)
tc_gemm(const __nv_bfloat16* __restrict__ Ah, const __nv_bfloat16* __restrict__ Al,
        const __nv_bfloat16* __restrict__ Bh, const __nv_bfloat16* __restrict__ Bl,
        float* __restrict__ C)
{
    extern __shared__ __nv_bfloat16 smb[];
    const uint32_t sb = smem_u32(smb);
    const int tid  = threadIdx.x;
    const int lane = tid & 31;
    const int wid  = tid >> 5;
    const int bn   = blockIdx.x * 128;
    const int bm   = blockIdx.y * 128;
    const int wm   = (wid >> 2) * 64;     // warp m offset in tile
    const int wn   = (wid & 3) * 32;      // warp n offset in tile

    float acc[4][4][4];
#pragma unroll
    for (int i = 0; i < 4; i++)
#pragma unroll
        for (int j = 0; j < 4; j++)
#pragma unroll
            for (int v = 0; v < 4; v++) acc[i][j][v] = 0.f;

    // ldmatrix lane address components
    const int lmA = lane & 15;                     // A row within m16
    const int lkA = (lane >> 4) * 16;              // A k-byte offset (0 or 16)
    const int rB  = (lane & 7) + ((lane >> 4) << 3);  // B row (n) within n16 pair
    const int lkB = (((lane >> 3) & 1) << 3) * 2;  // B k-byte offset (0 or 16)

    stage_load(Ah, Al, Bh, Bl, bm, bn, 0, sb, tid);
    CP_COMMIT();

#pragma unroll 1
    for (int kt = 0; kt < 32; kt++) {
        if (kt + 1 < 32) {
            stage_load(Ah, Al, Bh, Bl, bm, bn, kt + 1,
                       sb + ((kt + 1) & 1) * STG_BYTES, tid);
            CP_COMMIT();
            CP_WAIT1();
        } else {
            CP_WAIT0();
        }
        __syncthreads();

        const uint32_t st = sb + (kt & 1) * STG_BYTES;
#pragma unroll
        for (int ks = 0; ks < 2; ks++) {
            uint32_t ah[4][4], al[4][4], bh[2][4], bl[2][4];
#pragma unroll
            for (int mt = 0; mt < 4; mt++) {
                uint32_t a = st + (wm + mt * 16 + lmA) * (PAD * 2) + lkA + ks * 32;
                ldsm4(ah[mt], a);
                ldsm4(al[mt], a + MAT_BYTES);
            }
#pragma unroll
            for (int p = 0; p < 2; p++) {
                uint32_t a = st + 2 * MAT_BYTES
                           + (wn + p * 16 + rB) * (PAD * 2) + lkB + ks * 32;
                ldsm4(bh[p], a);
                ldsm4(bl[p], a + MAT_BYTES);
            }
#pragma unroll
            for (int mt = 0; mt < 4; mt++)
#pragma unroll
                for (int nt = 0; nt < 4; nt++) {
                    float* cc = acc[mt][nt];
                    const uint32_t* bhp = &bh[nt >> 1][(nt & 1) * 2];
                    const uint32_t* blp = &bl[nt >> 1][(nt & 1) * 2];
                    mma16816(cc, ah[mt], bhp);   // hi*hi
                    mma16816(cc, ah[mt], blp);   // hi*lo
                    mma16816(cc, al[mt], bhp);   // lo*hi
                }
        }
        __syncthreads();
    }

    // epilogue: c0,c1 -> (row=m+lane/4, cols n+2*(lane%4)); c2,c3 -> row+8
    const int mr = lane >> 2, nc = (lane & 3) * 2;
#pragma unroll
    for (int mt = 0; mt < 4; mt++)
#pragma unroll
        for (int nt = 0; nt < 4; nt++) {
            int m = bm + wm + mt * 16 + mr;
            int n = bn + wn + nt * 8 + nc;
            *(float2*)&C[(size_t)m * 1024 + n] =
                make_float2(acc[mt][nt][0], acc[mt][nt][1]);
            *(float2*)&C[(size_t)(m + 8) * 1024 + n] =
                make_float2(acc[mt][nt][2], acc[mt][nt][3]);
        }
}

// ---------------------------------------------------------------------------
// NT SGEMM (FFMA2, conflict-free) — used for Kp/Vp
// ---------------------------------------------------------------------------
__global__ void __launch_bounds__(256, 2)
sgemm_nt(const float* __restrict__ A,
         const float* __restrict__ B0, const float* __restrict__ B1,
         float* __restrict__ C0, float* __restrict__ C1,
         int M, int N, int K)
{
    const float* Bm = blockIdx.z ? B1 : B0;
    float*       C  = blockIdx.z ? C1 : C0;

    __shared__ float As[8][128];
    __shared__ float Bs[8][128];

    const int bm  = blockIdx.y * 128;
    const int bn  = blockIdx.x * 128;
    const int tid = threadIdx.x;
    const int lane = tid & 31;
    const int w    = tid >> 5;

    const int ar = tid >> 1;
    const int ac = (tid & 1) * 4;
    const float* Ap = A  + (size_t)(bm + ar) * K + ac;
    const float* Bp = Bm + (size_t)(bn + ar) * K + ac;

    float4 a4 = *(const float4*)Ap;
    float4 b4 = *(const float4*)Bp;

    const int r0 = (w & 3) * 32 + (lane >> 3) * 8;
    const int ca = (w >> 2) * 64 + (lane & 7) * 4;
    const int cb = ca + 32;

    ull acc[8][4];
#pragma unroll
    for (int i = 0; i < 8; i++)
#pragma unroll
        for (int j = 0; j < 4; j++) acc[i][j] = 0ull;

    for (int kt = 0; kt < K; kt += 8) {
        As[ac + 0][ar] = a4.x; As[ac + 1][ar] = a4.y;
        As[ac + 2][ar] = a4.z; As[ac + 3][ar] = a4.w;
        Bs[ac + 0][ar] = b4.x; Bs[ac + 1][ar] = b4.y;
        Bs[ac + 2][ar] = b4.z; Bs[ac + 3][ar] = b4.w;
        __syncthreads();

        if (kt + 8 < K) {
            a4 = *(const float4*)(Ap + kt + 8);
            b4 = *(const float4*)(Bp + kt + 8);
        }

#pragma unroll
        for (int k = 0; k < 8; k++) {
            float4 A0 = *(const float4*)&As[k][r0];
            float4 A1 = *(const float4*)&As[k][r0 + 4];
            ulonglong2 bb0 = *(const ulonglong2*)&Bs[k][ca];
            ulonglong2 bb1 = *(const ulonglong2*)&Bs[k][cb];
            float av[8] = {A0.x, A0.y, A0.z, A0.w, A1.x, A1.y, A1.z, A1.w};
#pragma unroll
            for (int i = 0; i < 8; i++) {
                ull ad = dup2(av[i]);
                fma2(acc[i][0], ad, bb0.x);
                fma2(acc[i][1], ad, bb0.y);
                fma2(acc[i][2], ad, bb1.x);
                fma2(acc[i][3], ad, bb1.y);
            }
        }
        __syncthreads();
    }

#pragma unroll
    for (int i = 0; i < 8; i++) {
        float2 p0 = upk(acc[i][0]), p1 = upk(acc[i][1]);
        float2 p2 = upk(acc[i][2]), p3 = upk(acc[i][3]);
        float* Cr = C + (size_t)(bm + r0 + i) * N + bn;
        *(float4*)(Cr + ca) = make_float4(p0.x, p0.y, p1.x, p1.y);
        *(float4*)(Cr + cb) = make_float4(p2.x, p2.y, p3.x, p3.y);
    }
}

// ---------------------------------------------------------------------------
// TN GEMM: xp[b,e,f] = sum_n proj[n,e] * x[b,n,f]
// ---------------------------------------------------------------------------
__global__ void __launch_bounds__(256)
proj_gemm(const float* __restrict__ x, const float* __restrict__ proj)
{
    __shared__ float As[16][64];
    __shared__ float Bs[16][128];

    const int f0 = blockIdx.x * 128;
    const int e0 = blockIdx.y * 64;
    const int b  = blockIdx.z;
    const int tid = threadIdx.x;
    const int lane = tid & 31;
    const int w    = tid >> 5;

    const int r0 = (w & 3) * 16 + (lane >> 3) * 4;
    const int ca = (w >> 2) * 64 + (lane & 7) * 4;
    const int cb = ca + 32;

    const float* xb = x + (size_t)b * N_ * F_;

    ull acc[4][4];
#pragma unroll
    for (int i = 0; i < 4; i++)
#pragma unroll
        for (int j = 0; j < 4; j++) acc[i][j] = 0ull;

    for (int n0 = 0; n0 < N_; n0 += 16) {
        {
            int r = tid >> 4, cv = tid & 15;
            *(float4*)&As[r][cv * 4] =
                *(const float4*)(proj + (size_t)(n0 + r) * E_ + e0 + cv * 4);
        }
#pragma unroll
        for (int t = 0; t < 2; t++) {
            int idx = tid + t * 256;
            int r = idx >> 5, cv = idx & 31;
            *(float4*)&Bs[r][cv * 4] =
                *(const float4*)(xb + (size_t)(n0 + r) * F_ + f0 + cv * 4);
        }
        __syncthreads();

#pragma unroll
        for (int k = 0; k < 16; k++) {
            float4 a = *(const float4*)&As[k][r0];
            ulonglong2 bb0 = *(const ulonglong2*)&Bs[k][ca];
            ulonglong2 bb1 = *(const ulonglong2*)&Bs[k][cb];
            float av[4] = {a.x, a.y, a.z, a.w};
#pragma unroll
            for (int i = 0; i < 4; i++) {
                ull ad = dup2(av[i]);
                fma2(acc[i][0], ad, bb0.x);
                fma2(acc[i][1], ad, bb0.y);
                fma2(acc[i][2], ad, bb1.x);
                fma2(acc[i][3], ad, bb1.y);
            }
        }
        __syncthreads();
    }

    float* Cb = g_xp + (size_t)b * E_ * F_;
#pragma unroll
    for (int i = 0; i < 4; i++) {
        float2 p0 = upk(acc[i][0]), p1 = upk(acc[i][1]);
        float2 p2 = upk(acc[i][2]), p3 = upk(acc[i][3]);
        float* Cr = Cb + (size_t)(e0 + r0 + i) * F_ + f0;
        *(float4*)(Cr + ca) = make_float4(p0.x, p0.y, p1.x, p1.y);
        *(float4*)(Cr + cb) = make_float4(p2.x, p2.y, p3.x, p3.y);
    }
}

// ---------------------------------------------------------------------------
// Persistent fused attention (FFMA2). Writes ao as split hi/lo bf16.
// ---------------------------------------------------------------------------
__global__ void __launch_bounds__(256, 1)
attn_kernel()
{
    extern __shared__ float sm[];
    float* Ks = sm;                    // [d][e]   64*256
    float* Vs = Ks + 64 * E_;          // [e][d]   256*64
    float* Qw = Vs + E_ * 64;          // [warp][8][64]
    float* Sw = Qw + 8 * 8 * 64;       // [warp][8][256]

    const int h  = blockIdx.y;
    const int b  = blockIdx.z;
    const int tid  = threadIdx.x;
    const int lane = tid & 31;
    const int w    = tid >> 5;

    const float* kpb = g_kp + (size_t)b * E_ * F_ + h * D_;
    const float* vpb = g_vp + (size_t)b * E_ * F_ + h * D_;

    for (int idx = tid; idx < E_ * 16; idx += 256) {
        int e = idx >> 4, d4 = (idx & 15) << 2;
        float4 v = *(const float4*)(kpb + (size_t)e * F_ + d4);
        Ks[(d4 + 0) * E_ + e] = v.x;
        Ks[(d4 + 1) * E_ + e] = v.y;
        Ks[(d4 + 2) * E_ + e] = v.z;
        Ks[(d4 + 3) * E_ + e] = v.w;
        float4 u = *(const float4*)(vpb + (size_t)e * F_ + d4);
        *(float4*)(Vs + e * 64 + d4) = u;
    }
    __syncthreads();

    float* Qm = Qw + w * 8 * 64;
    float* Sm = Sw + w * 8 * 256;
    const int d0 = lane * 2;
    const int ea = lane * 4;
    const int eb = 128 + lane * 4;

    for (int t = blockIdx.x; t < N_ / 64; t += SPLIT) {
        const int n0 = t * 64 + w * 8;
        const float* qp = g_q + (size_t)(b * N_ + n0) * F_ + h * D_;

#pragma unroll
        for (int s = 0; s < 4; s++) {
            int idx = s * 32 + lane;
            int r = idx >> 4, c = (idx & 15) * 4;
            float4 v = *(const float4*)(qp + (size_t)r * F_ + c);
            *(float4*)(Qm + r * 64 + c) =
                make_float4(v.x * 0.125f, v.y * 0.125f, v.z * 0.125f, v.w * 0.125f);
        }
        __syncwarp();

        ull c2[8][4];
#pragma unroll
        for (int i = 0; i < 8; i++)
#pragma unroll
            for (int jp = 0; jp < 4; jp++) c2[i][jp] = 0ull;

        for (int dc = 0; dc < 64; dc += 4) {
            ull ka[4][2], kb[4][2];
#pragma unroll
            for (int dd = 0; dd < 4; dd++) {
                ulonglong2 t0 = *(const ulonglong2*)&Ks[(dc + dd) * E_ + ea];
                ulonglong2 t1 = *(const ulonglong2*)&Ks[(dc + dd) * E_ + eb];
                ka[dd][0] = t0.x; ka[dd][1] = t0.y;
                kb[dd][0] = t1.x; kb[dd][1] = t1.y;
            }
#pragma unroll
            for (int i = 0; i < 8; i++) {
                float4 q = *(const float4*)&Qm[i * 64 + dc];
                float qa[4] = {q.x, q.y, q.z, q.w};
#pragma unroll
                for (int dd = 0; dd < 4; dd++) {
                    ull qd = dup2(qa[dd]);
                    fma2(c2[i][0], qd, ka[dd][0]);
                    fma2(c2[i][1], qd, ka[dd][1]);
                    fma2(c2[i][2], qd, kb[dd][0]);
                    fma2(c2[i][3], qd, kb[dd][1]);
                }
            }
        }

#pragma unroll
        for (int i = 0; i < 8; i++) {
            float2 v0 = upk(c2[i][0]), v1 = upk(c2[i][1]);
            float2 v2 = upk(c2[i][2]), v3 = upk(c2[i][3]);
            float va[8] = {v0.x, v0.y, v1.x, v1.y, v2.x, v2.y, v3.x, v3.y};
            float m = va[0];
#pragma unroll
            for (int j = 1; j < 8; j++) m = fmaxf(m, va[j]);
#pragma unroll
            for (int o = 16; o > 0; o >>= 1)
                m = fmaxf(m, __shfl_xor_sync(0xffffffffu, m, o));
            float s = 0.f;
#pragma unroll
            for (int j = 0; j < 8; j++) { va[j] = __expf(va[j] - m); s += va[j]; }
#pragma unroll
            for (int o = 16; o > 0; o >>= 1)
                s += __shfl_xor_sync(0xffffffffu, s, o);
            float inv = 1.f / s;
#pragma unroll
            for (int j = 0; j < 8; j++) va[j] *= inv;
            *(float4*)&Sm[i * E_ + ea] = make_float4(va[0], va[1], va[2], va[3]);
            *(float4*)&Sm[i * E_ + eb] = make_float4(va[4], va[5], va[6], va[7]);
        }
        __syncwarp();

        ull acc[8];
#pragma unroll
        for (int i = 0; i < 8; i++) acc[i] = 0ull;

        for (int e = 0; e < E_; e += 4) {
            ull vv[4];
#pragma unroll
            for (int k4 = 0; k4 < 4; k4++)
                vv[k4] = *(const ull*)&Vs[(e + k4) * 64 + d0];
#pragma unroll
            for (int i = 0; i < 8; i++) {
                float4 aa = *(const float4*)&Sm[i * E_ + e];
                fma2(acc[i], dup2(aa.x), vv[0]);
                fma2(acc[i], dup2(aa.y), vv[1]);
                fma2(acc[i], dup2(aa.z), vv[2]);
                fma2(acc[i], dup2(aa.w), vv[3]);
            }
        }

        const size_t obase = (size_t)(b * N_ + n0) * F_ + h * D_ + d0;
#pragma unroll
        for (int i = 0; i < 8; i++) {
            float2 o = upk(acc[i]);
            __nv_bfloat16 hx = __float2bfloat16(o.x);
            __nv_bfloat16 hy = __float2bfloat16(o.y);
            __nv_bfloat16 lx = __float2bfloat16(o.x - __bfloat162float(hx));
            __nv_bfloat16 ly = __float2bfloat16(o.y - __bfloat162float(hy));
            size_t p = obase + (size_t)i * F_;
            *(__nv_bfloat162*)(g_aoh + p) = __nv_bfloat162(hx, hy);
            *(__nv_bfloat162*)(g_aol + p) = __nv_bfloat162(lx, ly);
        }
    }
}

// ---------------------------------------------------------------------------
extern "C" void kernel_launch(void* const* d_in, const int* in_sizes, int n_in,
                              void* d_out, int out_size)
{
    (void)in_sizes; (void)n_in; (void)out_size;
    const float* x    = (const float*)d_in[0];
    const float* proj = (const float*)d_in[1];
    const float* Wq   = (const float*)d_in[2];
    const float* Wk   = (const float*)d_in[3];
    const float* Wv   = (const float*)d_in[4];
    const float* Wo   = (const float*)d_in[5];
    float* out = (float*)d_out;

    float *pq, *pxp, *pkp, *pvp;
    cudaGetSymbolAddress((void**)&pq,  g_q);
    cudaGetSymbolAddress((void**)&pxp, g_xp);
    cudaGetSymbolAddress((void**)&pkp, g_kp);
    cudaGetSymbolAddress((void**)&pvp, g_vp);
    __nv_bfloat16 *xh, *xl, *aoh, *aol, *wqh, *wql, *woh, *wol;
    cudaGetSymbolAddress((void**)&xh,  g_xh);
    cudaGetSymbolAddress((void**)&xl,  g_xl);
    cudaGetSymbolAddress((void**)&aoh, g_aoh);
    cudaGetSymbolAddress((void**)&aol, g_aol);
    cudaGetSymbolAddress((void**)&wqh, g_wqh);
    cudaGetSymbolAddress((void**)&wql, g_wql);
    cudaGetSymbolAddress((void**)&woh, g_woh);
    cudaGetSymbolAddress((void**)&wol, g_wol);

    const size_t ATT_SMEM =
        (size_t)(64 * E_ + E_ * 64 + 8 * 8 * 64 + 8 * 8 * E_) * sizeof(float);
    cudaFuncSetAttribute(attn_kernel,
                         cudaFuncAttributeMaxDynamicSharedMemorySize, (int)ATT_SMEM);
    cudaFuncSetAttribute(tc_gemm,
                         cudaFuncAttributeMaxDynamicSharedMemorySize, TCG_SMEM);

    // 0) split fp32 -> bf16 hi/lo
    split_bf16<<<(B_*N_*F_/4 + 255)/256, 256>>>(x,  xh,  xl,  B_*N_*F_/4);
    split_bf16<<<(F_*F_/4 + 255)/256, 256>>>(Wq, wqh, wql, F_*F_/4);
    split_bf16<<<(F_*F_/4 + 255)/256, 256>>>(Wo, woh, wol, F_*F_/4);
    // 1) xp = proj^T @ x (per batch)
    proj_gemm<<<dim3(8, 4, 4), 256>>>(x, proj);
    // 2) Kp = xp @ Wk^T ; Vp = xp @ Wv^T
    sgemm_nt<<<dim3(8, 8, 2), 256>>>(pxp, Wk, Wv, pkp, pvp, B_ * E_, F_, F_);
    // 3) Q = x @ Wq^T   (HMMA split-bf16)
    tc_gemm<<<dim3(8, 128), 256, TCG_SMEM>>>(xh, xl, wqh, wql, pq);
    // 4) fused persistent attention -> ao (hi/lo bf16)
    attn_kernel<<<dim3(SPLIT, H_, B_), 256, ATT_SMEM>>>();
    // 5) out = ao @ Wo^T (HMMA split-bf16)
    tc_gemm<<<dim3(8, 128), 256, TCG_SMEM>>>(aoh, aol, woh, wol, out);
}

// round 6
// speedup vs baseline: 2.0752x; 1.0688x over previous
#include <cuda_runtime.h>
#include <cuda_bf16.h>
#include <cstdint>

#define B_ 4
#define N_ 4096
#define F_ 1024
#define H_ 16
#define D_ 64
#define E_ 256
#define SPLIT 2
#define KSPLIT 4

typedef unsigned long long ull;

// ---- packed f32x2 helpers (sm_103a native FFMA2) ----
__device__ __forceinline__ ull dup2(float v) {
    ull r; asm("mov.b64 %0, {%1, %1};" : "=l"(r) : "f"(v)); return r;
}
__device__ __forceinline__ void fma2(ull& d, ull a, ull b) {
    asm("fma.rn.f32x2 %0, %1, %2, %0;" : "+l"(d) : "l"(a), "l"(b));
}
__device__ __forceinline__ float2 upk(ull v) {
    float2 f; asm("mov.b64 {%0, %1}, %2;" : "=f"(f.x), "=f"(f.y) : "l"(v)); return f;
}

// ---- portable tensor-core helpers ----
__device__ __forceinline__ uint32_t smem_u32(const void* p) {
    uint32_t a;
    asm("{ .reg .u64 t; cvta.to.shared.u64 t, %1; cvt.u32.u64 %0, t; }" : "=r"(a) : "l"(p));
    return a;
}
__device__ __forceinline__ void ldsm4(uint32_t* r, uint32_t a) {
    asm volatile("ldmatrix.sync.aligned.m8n8.x4.shared.b16 {%0,%1,%2,%3}, [%4];"
        : "=r"(r[0]), "=r"(r[1]), "=r"(r[2]), "=r"(r[3]) : "r"(a));
}
__device__ __forceinline__ void mma16816(float* c, const uint32_t* a, const uint32_t* b) {
    asm volatile("mma.sync.aligned.m16n8k16.row.col.f32.bf16.bf16.f32 "
        "{%0,%1,%2,%3}, {%4,%5,%6,%7}, {%8,%9}, {%0,%1,%2,%3};"
        : "+f"(c[0]), "+f"(c[1]), "+f"(c[2]), "+f"(c[3])
        : "r"(a[0]), "r"(a[1]), "r"(a[2]), "r"(a[3]), "r"(b[0]), "r"(b[1]));
}
#define CP16(dst, src) asm volatile("cp.async.cg.shared.global [%0], [%1], 16;" :: "r"(dst), "l"(src))
#define CP_COMMIT()    asm volatile("cp.async.commit_group;" ::: "memory")
#define CP_WAIT1()     asm volatile("cp.async.wait_group 1;" ::: "memory")
#define CP_WAIT0()     asm volatile("cp.async.wait_group 0;" ::: "memory")

// ---- scratch (device globals) ----
__device__ float g_q  [B_*N_*F_];
__device__ float g_xp [B_*E_*F_];
__device__ float g_xpp[KSPLIT*B_*E_*F_];   // split-K partials
__device__ float g_kp [B_*E_*F_];
__device__ float g_vp [B_*E_*F_];
__device__ __nv_bfloat16 g_xh [B_*N_*F_], g_xl [B_*N_*F_];
__device__ __nv_bfloat16 g_aoh[B_*N_*F_], g_aol[B_*N_*F_];
__device__ __nv_bfloat16 g_wqh[F_*F_], g_wql[F_*F_];
__device__ __nv_bfloat16 g_woh[F_*F_], g_wol[F_*F_];

// ---------------------------------------------------------------------------
// split fp32 -> (hi, lo) bf16
// ---------------------------------------------------------------------------
__global__ void __launch_bounds__(256)
split_bf16(const float* __restrict__ in, __nv_bfloat16* __restrict__ hi,
           __nv_bfloat16* __restrict__ lo, int n4)
{
    int i = blockIdx.x * 256 + threadIdx.x;
    if (i >= n4) return;
    float4 v = ((const float4*)in)[i];
    __nv_bfloat16 h0 = __float2bfloat16(v.x), h1 = __float2bfloat16(v.y);
    __nv_bfloat16 h2 = __float2bfloat16(v.z), h3 = __float2bfloat16(v.w);
    __nv_bfloat16 l0 = __float2bfloat16(v.x - __bfloat162float(h0));
    __nv_bfloat16 l1 = __float2bfloat16(v.y - __bfloat162float(h1));
    __nv_bfloat16 l2 = __float2bfloat16(v.z - __bfloat162float(h2));
    __nv_bfloat16 l3 = __float2bfloat16(v.w - __bfloat162float(h3));
    ((__nv_bfloat162*)hi)[i*2]   = __nv_bfloat162(h0, h1);
    ((__nv_bfloat162*)hi)[i*2+1] = __nv_bfloat162(h2, h3);
    ((__nv_bfloat162*)lo)[i*2]   = __nv_bfloat162(l0, l1);
    ((__nv_bfloat162*)lo)[i*2+1] = __nv_bfloat162(l2, l3);
}

// ---------------------------------------------------------------------------
// Tensor-core split-bf16 NT GEMM (mma.sync m16n8k16), 3-stage cp.async.
// CTA 128x128, BK=32, 8 warps (warp 64x32). PAD=40 rows.
// ---------------------------------------------------------------------------
#define PAD        40
#define MAT_BYTES  (128 * PAD * 2)
#define STG_BYTES  (4 * MAT_BYTES)
#define TCG_SMEM   (3 * STG_BYTES)        // 122880 B

__device__ __forceinline__ void stage_load(
    const __nv_bfloat16* __restrict__ Ah, const __nv_bfloat16* __restrict__ Al,
    const __nv_bfloat16* __restrict__ Bh, const __nv_bfloat16* __restrict__ Bl,
    int bm, int bn, int kt, uint32_t sbase, int tid)
{
    const __nv_bfloat16* gp[4] = {
        Ah + (size_t)bm * 1024, Al + (size_t)bm * 1024,
        Bh + (size_t)bn * 1024, Bl + (size_t)bn * 1024 };
#pragma unroll
    for (int m = 0; m < 4; m++) {
        const __nv_bfloat16* base = gp[m] + kt * 32;
        uint32_t sb = sbase + m * MAT_BYTES;
#pragma unroll
        for (int it = 0; it < 2; it++) {
            int c = tid + it * 256;
            int row = c >> 2, q = c & 3;
            CP16(sb + row * (PAD * 2) + q * 16, base + (size_t)row * 1024 + q * 8);
        }
    }
}

__global__ void __launch_bounds__(256, 1)
tc_gemm(const __nv_bfloat16* __restrict__ Ah, const __nv_bfloat16* __restrict__ Al,
        const __nv_bfloat16* __restrict__ Bh, const __nv_bfloat16* __restrict__ Bl,
        float* __restrict__ C)
{
    extern __shared__ __nv_bfloat16 smb[];
    const uint32_t sb = smem_u32(smb);
    const int tid  = threadIdx.x;
    const int lane = tid & 31;
    const int wid  = tid >> 5;
    const int bn   = blockIdx.x * 128;
    const int bm   = blockIdx.y * 128;
    const int wm   = (wid >> 2) * 64;
    const int wn   = (wid & 3) * 32;

    float acc[4][4][4];
#pragma unroll
    for (int i = 0; i < 4; i++)
#pragma unroll
        for (int j = 0; j < 4; j++)
#pragma unroll
            for (int v = 0; v < 4; v++) acc[i][j][v] = 0.f;

    const int lmA = lane & 15;
    const int lkA = (lane >> 4) * 16;
    const int rB  = (lane & 7) + ((lane >> 4) << 3);
    const int lkB = (((lane >> 3) & 1) << 3) * 2;

    stage_load(Ah, Al, Bh, Bl, bm, bn, 0, sb, tid);
    CP_COMMIT();
    stage_load(Ah, Al, Bh, Bl, bm, bn, 1, sb + STG_BYTES, tid);
    CP_COMMIT();

#pragma unroll 1
    for (int kt = 0; kt < 32; kt++) {
        if (kt + 2 < 32) { CP_WAIT1(); } else { CP_WAIT0(); }
        __syncthreads();
        if (kt + 2 < 32) {
            stage_load(Ah, Al, Bh, Bl, bm, bn, kt + 2,
                       sb + ((kt + 2) % 3) * STG_BYTES, tid);
            CP_COMMIT();
        }

        const uint32_t st = sb + (kt % 3) * STG_BYTES;
#pragma unroll
        for (int ks = 0; ks < 2; ks++) {
            uint32_t ah[4][4], al[4][4], bh[2][4], bl[2][4];
#pragma unroll
            for (int mt = 0; mt < 4; mt++) {
                uint32_t a = st + (wm + mt * 16 + lmA) * (PAD * 2) + lkA + ks * 32;
                ldsm4(ah[mt], a);
                ldsm4(al[mt], a + MAT_BYTES);
            }
#pragma unroll
            for (int p = 0; p < 2; p++) {
                uint32_t a = st + 2 * MAT_BYTES
                           + (wn + p * 16 + rB) * (PAD * 2) + lkB + ks * 32;
                ldsm4(bh[p], a);
                ldsm4(bl[p], a + MAT_BYTES);
            }
#pragma unroll
            for (int mt = 0; mt < 4; mt++)
#pragma unroll
                for (int nt = 0; nt < 4; nt++) {
                    float* cc = acc[mt][nt];
                    const uint32_t* bhp = &bh[nt >> 1][(nt & 1) * 2];
                    const uint32_t* blp = &bl[nt >> 1][(nt & 1) * 2];
                    mma16816(cc, ah[mt], bhp);
                    mma16816(cc, ah[mt], blp);
                    mma16816(cc, al[mt], bhp);
                }
        }
    }
    __syncthreads();

    const int mr = lane >> 2, nc = (lane & 3) * 2;
#pragma unroll
    for (int mt = 0; mt < 4; mt++)
#pragma unroll
        for (int nt = 0; nt < 4; nt++) {
            int m = bm + wm + mt * 16 + mr;
            int n = bn + wn + nt * 8 + nc;
            *(float2*)&C[(size_t)m * 1024 + n] =
                make_float2(acc[mt][nt][0], acc[mt][nt][1]);
            *(float2*)&C[(size_t)(m + 8) * 1024 + n] =
                make_float2(acc[mt][nt][2], acc[mt][nt][3]);
        }
}

// ---------------------------------------------------------------------------
// NT SGEMM (FFMA2, conflict-free) — used for Kp/Vp
// ---------------------------------------------------------------------------
__global__ void __launch_bounds__(256, 2)
sgemm_nt(const float* __restrict__ A,
         const float* __restrict__ B0, const float* __restrict__ B1,
         float* __restrict__ C0, float* __restrict__ C1,
         int M, int N, int K)
{
    const float* Bm = blockIdx.z ? B1 : B0;
    float*       C  = blockIdx.z ? C1 : C0;

    __shared__ float As[8][128];
    __shared__ float Bs[8][128];

    const int bm  = blockIdx.y * 128;
    const int bn  = blockIdx.x * 128;
    const int tid = threadIdx.x;
    const int lane = tid & 31;
    const int w    = tid >> 5;

    const int ar = tid >> 1;
    const int ac = (tid & 1) * 4;
    const float* Ap = A  + (size_t)(bm + ar) * K + ac;
    const float* Bp = Bm + (size_t)(bn + ar) * K + ac;

    float4 a4 = *(const float4*)Ap;
    float4 b4 = *(const float4*)Bp;

    const int r0 = (w & 3) * 32 + (lane >> 3) * 8;
    const int ca = (w >> 2) * 64 + (lane & 7) * 4;
    const int cb = ca + 32;

    ull acc[8][4];
#pragma unroll
    for (int i = 0; i < 8; i++)
#pragma unroll
        for (int j = 0; j < 4; j++) acc[i][j] = 0ull;

    for (int kt = 0; kt < K; kt += 8) {
        As[ac + 0][ar] = a4.x; As[ac + 1][ar] = a4.y;
        As[ac + 2][ar] = a4.z; As[ac + 3][ar] = a4.w;
        Bs[ac + 0][ar] = b4.x; Bs[ac + 1][ar] = b4.y;
        Bs[ac + 2][ar] = b4.z; Bs[ac + 3][ar] = b4.w;
        __syncthreads();

        if (kt + 8 < K) {
            a4 = *(const float4*)(Ap + kt + 8);
            b4 = *(const float4*)(Bp + kt + 8);
        }

#pragma unroll
        for (int k = 0; k < 8; k++) {
            float4 A0 = *(const float4*)&As[k][r0];
            float4 A1 = *(const float4*)&As[k][r0 + 4];
            ulonglong2 bb0 = *(const ulonglong2*)&Bs[k][ca];
            ulonglong2 bb1 = *(const ulonglong2*)&Bs[k][cb];
            float av[8] = {A0.x, A0.y, A0.z, A0.w, A1.x, A1.y, A1.z, A1.w};
#pragma unroll
            for (int i = 0; i < 8; i++) {
                ull ad = dup2(av[i]);
                fma2(acc[i][0], ad, bb0.x);
                fma2(acc[i][1], ad, bb0.y);
                fma2(acc[i][2], ad, bb1.x);
                fma2(acc[i][3], ad, bb1.y);
            }
        }
        __syncthreads();
    }

#pragma unroll
    for (int i = 0; i < 8; i++) {
        float2 p0 = upk(acc[i][0]), p1 = upk(acc[i][1]);
        float2 p2 = upk(acc[i][2]), p3 = upk(acc[i][3]);
        float* Cr = C + (size_t)(bm + r0 + i) * N + bn;
        *(float4*)(Cr + ca) = make_float4(p0.x, p0.y, p1.x, p1.y);
        *(float4*)(Cr + cb) = make_float4(p2.x, p2.y, p3.x, p3.y);
    }
}

// ---------------------------------------------------------------------------
// TN GEMM split-K: xpp[ks][b,e,f] = sum_{n in ks-slice} proj[n,e] * x[b,n,f]
// grid (8, 4, B*KSPLIT)
// ---------------------------------------------------------------------------
__global__ void __launch_bounds__(256)
proj_gemm(const float* __restrict__ x, const float* __restrict__ proj)
{
    __shared__ float As[16][64];
    __shared__ float Bs[16][128];

    const int f0 = blockIdx.x * 128;
    const int e0 = blockIdx.y * 64;
    const int b  = blockIdx.z >> 2;
    const int ks = blockIdx.z & 3;
    const int tid = threadIdx.x;
    const int lane = tid & 31;
    const int w    = tid >> 5;

    const int r0 = (w & 3) * 16 + (lane >> 3) * 4;
    const int ca = (w >> 2) * 64 + (lane & 7) * 4;
    const int cb = ca + 32;

    const float* xb = x + (size_t)b * N_ * F_;
    const int nlo = ks * (N_ / KSPLIT), nhi = nlo + N_ / KSPLIT;

    ull acc[4][4];
#pragma unroll
    for (int i = 0; i < 4; i++)
#pragma unroll
        for (int j = 0; j < 4; j++) acc[i][j] = 0ull;

    for (int n0 = nlo; n0 < nhi; n0 += 16) {
        {
            int r = tid >> 4, cv = tid & 15;
            *(float4*)&As[r][cv * 4] =
                *(const float4*)(proj + (size_t)(n0 + r) * E_ + e0 + cv * 4);
        }
#pragma unroll
        for (int t = 0; t < 2; t++) {
            int idx = tid + t * 256;
            int r = idx >> 5, cv = idx & 31;
            *(float4*)&Bs[r][cv * 4] =
                *(const float4*)(xb + (size_t)(n0 + r) * F_ + f0 + cv * 4);
        }
        __syncthreads();

#pragma unroll
        for (int k = 0; k < 16; k++) {
            float4 a = *(const float4*)&As[k][r0];
            ulonglong2 bb0 = *(const ulonglong2*)&Bs[k][ca];
            ulonglong2 bb1 = *(const ulonglong2*)&Bs[k][cb];
            float av[4] = {a.x, a.y, a.z, a.w};
#pragma unroll
            for (int i = 0; i < 4; i++) {
                ull ad = dup2(av[i]);
                fma2(acc[i][0], ad, bb0.x);
                fma2(acc[i][1], ad, bb0.y);
                fma2(acc[i][2], ad, bb1.x);
                fma2(acc[i][3], ad, bb1.y);
            }
        }
        __syncthreads();
    }

    float* Cb = g_xpp + (size_t)ks * (B_ * E_ * F_) + (size_t)b * E_ * F_;
#pragma unroll
    for (int i = 0; i < 4; i++) {
        float2 p0 = upk(acc[i][0]), p1 = upk(acc[i][1]);
        float2 p2 = upk(acc[i][2]), p3 = upk(acc[i][3]);
        float* Cr = Cb + (size_t)(e0 + r0 + i) * F_ + f0;
        *(float4*)(Cr + ca) = make_float4(p0.x, p0.y, p1.x, p1.y);
        *(float4*)(Cr + cb) = make_float4(p2.x, p2.y, p3.x, p3.y);
    }
}

__global__ void __launch_bounds__(256)
xp_reduce()
{
    int i = blockIdx.x * 256 + threadIdx.x;      // float4 index
    const int tot = B_ * E_ * F_ / 4;
    if (i >= tot) return;
    const float4* p0 = (const float4*)g_xpp;
    float4 a = p0[i];
    float4 b = p0[i + tot];
    float4 c = p0[i + 2 * tot];
    float4 d = p0[i + 3 * tot];
    ((float4*)g_xp)[i] = make_float4(a.x + b.x + c.x + d.x,
                                     a.y + b.y + c.y + d.y,
                                     a.z + b.z + c.z + d.z,
                                     a.w + b.w + c.w + d.w);
}

// ---------------------------------------------------------------------------
// Persistent fused attention, 512 threads (16 warps x 4 queries).
// smem: K 64KB + V 64KB + Qw 16KB + Sw 64KB = 208KB.
// ---------------------------------------------------------------------------
__global__ void __launch_bounds__(512, 1)
attn_kernel()
{
    extern __shared__ float sm[];
    float* Ks = sm;                    // [d][e]   64*256
    float* Vs = Ks + 64 * E_;          // [e][d]   256*64
    float* Qw = Vs + E_ * 64;          // [warp][4][64]
    float* Sw = Qw + 16 * 4 * 64;      // [warp][4][256]

    const int h  = blockIdx.y;
    const int b  = blockIdx.z;
    const int tid  = threadIdx.x;
    const int lane = tid & 31;
    const int w    = tid >> 5;

    const float* kpb = g_kp + (size_t)b * E_ * F_ + h * D_;
    const float* vpb = g_vp + (size_t)b * E_ * F_ + h * D_;

    for (int idx = tid; idx < E_ * 16; idx += 512) {
        int e = idx >> 4, d4 = (idx & 15) << 2;
        float4 v = *(const float4*)(kpb + (size_t)e * F_ + d4);
        Ks[(d4 + 0) * E_ + e] = v.x;
        Ks[(d4 + 1) * E_ + e] = v.y;
        Ks[(d4 + 2) * E_ + e] = v.z;
        Ks[(d4 + 3) * E_ + e] = v.w;
        float4 u = *(const float4*)(vpb + (size_t)e * F_ + d4);
        *(float4*)(Vs + e * 64 + d4) = u;
    }
    __syncthreads();

    float* Qm = Qw + w * 4 * 64;
    float* Sm = Sw + w * 4 * 256;
    const int d0 = lane * 2;
    const int ea = lane * 4;
    const int eb = 128 + lane * 4;

    for (int t = blockIdx.x; t < N_ / 64; t += SPLIT) {
        const int n0 = t * 64 + w * 4;            // this warp's 4 query rows
        const float* qp = g_q + (size_t)(b * N_ + n0) * F_ + h * D_;

#pragma unroll
        for (int s = 0; s < 2; s++) {
            int idx = s * 32 + lane;
            int r = idx >> 4, c = (idx & 15) * 4;
            float4 v = *(const float4*)(qp + (size_t)r * F_ + c);
            *(float4*)(Qm + r * 64 + c) =
                make_float4(v.x * 0.125f, v.y * 0.125f, v.z * 0.125f, v.w * 0.125f);
        }
        __syncwarp();

        ull c2[4][4];
#pragma unroll
        for (int i = 0; i < 4; i++)
#pragma unroll
            for (int jp = 0; jp < 4; jp++) c2[i][jp] = 0ull;

        for (int dc = 0; dc < 64; dc += 4) {
            ull ka[4][2], kb[4][2];
#pragma unroll
            for (int dd = 0; dd < 4; dd++) {
                ulonglong2 t0 = *(const ulonglong2*)&Ks[(dc + dd) * E_ + ea];
                ulonglong2 t1 = *(const ulonglong2*)&Ks[(dc + dd) * E_ + eb];
                ka[dd][0] = t0.x; ka[dd][1] = t0.y;
                kb[dd][0] = t1.x; kb[dd][1] = t1.y;
            }
#pragma unroll
            for (int i = 0; i < 4; i++) {
                float4 q = *(const float4*)&Qm[i * 64 + dc];
                float qa[4] = {q.x, q.y, q.z, q.w};
#pragma unroll
                for (int dd = 0; dd < 4; dd++) {
                    ull qd = dup2(qa[dd]);
                    fma2(c2[i][0], qd, ka[dd][0]);
                    fma2(c2[i][1], qd, ka[dd][1]);
                    fma2(c2[i][2], qd, kb[dd][0]);
                    fma2(c2[i][3], qd, kb[dd][1]);
                }
            }
        }

#pragma unroll
        for (int i = 0; i < 4; i++) {
            float2 v0 = upk(c2[i][0]), v1 = upk(c2[i][1]);
            float2 v2 = upk(c2[i][2]), v3 = upk(c2[i][3]);
            float va[8] = {v0.x, v0.y, v1.x, v1.y, v2.x, v2.y, v3.x, v3.y};
            float m = va[0];
#pragma unroll
            for (int j = 1; j < 8; j++) m = fmaxf(m, va[j]);
#pragma unroll
            for (int o = 16; o > 0; o >>= 1)
                m = fmaxf(m, __shfl_xor_sync(0xffffffffu, m, o));
            float s = 0.f;
#pragma unroll
            for (int j = 0; j < 8; j++) { va[j] = __expf(va[j] - m); s += va[j]; }
#pragma unroll
            for (int o = 16; o > 0; o >>= 1)
                s += __shfl_xor_sync(0xffffffffu, s, o);
            float inv = 1.f / s;
#pragma unroll
            for (int j = 0; j < 8; j++) va[j] *= inv;
            *(float4*)&Sm[i * E_ + ea] = make_float4(va[0], va[1], va[2], va[3]);
            *(float4*)&Sm[i * E_ + eb] = make_float4(va[4], va[5], va[6], va[7]);
        }
        __syncwarp();

        ull acc[4];
#pragma unroll
        for (int i = 0; i < 4; i++) acc[i] = 0ull;

        for (int e = 0; e < E_; e += 4) {
            ull vv[4];
#pragma unroll
            for (int k4 = 0; k4 < 4; k4++)
                vv[k4] = *(const ull*)&Vs[(e + k4) * 64 + d0];
#pragma unroll
            for (int i = 0; i < 4; i++) {
                float4 aa = *(const float4*)&Sm[i * E_ + e];
                fma2(acc[i], dup2(aa.x), vv[0]);
                fma2(acc[i], dup2(aa.y), vv[1]);
                fma2(acc[i], dup2(aa.z), vv[2]);
                fma2(acc[i], dup2(aa.w), vv[3]);
            }
        }

        const size_t obase = (size_t)(b * N_ + n0) * F_ + h * D_ + d0;
#pragma unroll
        for (int i = 0; i < 4; i++) {
            float2 o = upk(acc[i]);
            __nv_bfloat16 hx = __float2bfloat16(o.x);
            __nv_bfloat16 hy = __float2bfloat16(o.y);
            __nv_bfloat16 lx = __float2bfloat16(o.x - __bfloat162float(hx));
            __nv_bfloat16 ly = __float2bfloat16(o.y - __bfloat162float(hy));
            size_t p = obase + (size_t)i * F_;
            *(__nv_bfloat162*)(g_aoh + p) = __nv_bfloat162(hx, hy);
            *(__nv_bfloat162*)(g_aol + p) = __nv_bfloat162(lx, ly);
        }
    }
}

// ---------------------------------------------------------------------------
extern "C" void kernel_launch(void* const* d_in, const int* in_sizes, int n_in,
                              void* d_out, int out_size)
{
    (void)in_sizes; (void)n_in; (void)out_size;
    const float* x    = (const float*)d_in[0];
    const float* proj = (const float*)d_in[1];
    const float* Wq   = (const float*)d_in[2];
    const float* Wk   = (const float*)d_in[3];
    const float* Wv   = (const float*)d_in[4];
    const float* Wo   = (const float*)d_in[5];
    float* out = (float*)d_out;

    float *pq, *pxp, *pkp, *pvp;
    cudaGetSymbolAddress((void**)&pq,  g_q);
    cudaGetSymbolAddress((void**)&pxp, g_xp);
    cudaGetSymbolAddress((void**)&pkp, g_kp);
    cudaGetSymbolAddress((void**)&pvp, g_vp);
    __nv_bfloat16 *xh, *xl, *aoh, *aol, *wqh, *wql, *woh, *wol;
    cudaGetSymbolAddress((void**)&xh,  g_xh);
    cudaGetSymbolAddress((void**)&xl,  g_xl);
    cudaGetSymbolAddress((void**)&aoh, g_aoh);
    cudaGetSymbolAddress((void**)&aol, g_aol);
    cudaGetSymbolAddress((void**)&wqh, g_wqh);
    cudaGetSymbolAddress((void**)&wql, g_wql);
    cudaGetSymbolAddress((void**)&woh, g_woh);
    cudaGetSymbolAddress((void**)&wol, g_wol);

    const size_t ATT_SMEM =
        (size_t)(64 * E_ + E_ * 64 + 16 * 4 * 64 + 16 * 4 * E_) * sizeof(float);
    cudaFuncSetAttribute(attn_kernel,
                         cudaFuncAttributeMaxDynamicSharedMemorySize, (int)ATT_SMEM);
    cudaFuncSetAttribute(tc_gemm,
                         cudaFuncAttributeMaxDynamicSharedMemorySize, TCG_SMEM);

    // 0) split fp32 -> bf16 hi/lo
    split_bf16<<<(B_*N_*F_/4 + 255)/256, 256>>>(x,  xh,  xl,  B_*N_*F_/4);
    split_bf16<<<(F_*F_/4 + 255)/256, 256>>>(Wq, wqh, wql, F_*F_/4);
    split_bf16<<<(F_*F_/4 + 255)/256, 256>>>(Wo, woh, wol, F_*F_/4);
    // 1) xp = proj^T @ x  (split-K x4 + reduce)
    proj_gemm<<<dim3(8, 4, B_ * KSPLIT), 256>>>(x, proj);
    xp_reduce<<<(B_*E_*F_/4 + 255)/256, 256>>>();
    // 2) Kp = xp @ Wk^T ; Vp = xp @ Wv^T
    sgemm_nt<<<dim3(8, 8, 2), 256>>>(pxp, Wk, Wv, pkp, pvp, B_ * E_, F_, F_);
    // 3) Q = x @ Wq^T   (HMMA split-bf16)
    tc_gemm<<<dim3(8, 128), 256, TCG_SMEM>>>(xh, xl, wqh, wql, pq);
    // 4) fused persistent attention -> ao (hi/lo bf16)
    attn_kernel<<<dim3(SPLIT, H_, B_), 512, ATT_SMEM>>>();
    // 5) out = ao @ Wo^T (HMMA split-bf16)
    tc_gemm<<<dim3(8, 128), 256, TCG_SMEM>>>(aoh, aol, woh, wol, out);
}

// round 7
// speedup vs baseline: 2.4293x; 1.1706x over previous
#include <cuda_runtime.h>
#include <cuda_bf16.h>
#include <cstdint>

#define B_ 4
#define N_ 4096
#define F_ 1024
#define H_ 16
#define D_ 64
#define E_ 256
#define SPLIT 2
#define KSPLIT 4

typedef unsigned long long ull;

// ---- packed f32x2 helpers ----
__device__ __forceinline__ ull dup2(float v) {
    ull r; asm("mov.b64 %0, {%1, %1};" : "=l"(r) : "f"(v)); return r;
}
__device__ __forceinline__ void fma2(ull& d, ull a, ull b) {
    asm("fma.rn.f32x2 %0, %1, %2, %0;" : "+l"(d) : "l"(a), "l"(b));
}
__device__ __forceinline__ float2 upk(ull v) {
    float2 f; asm("mov.b64 {%0, %1}, %2;" : "=f"(f.x), "=f"(f.y) : "l"(v)); return f;
}

// ---- tensor-core helpers (portable sm_80+) ----
__device__ __forceinline__ uint32_t smem_u32(const void* p) {
    uint32_t a;
    asm("{ .reg .u64 t; cvta.to.shared.u64 t, %1; cvt.u32.u64 %0, t; }" : "=r"(a) : "l"(p));
    return a;
}
__device__ __forceinline__ void ldsm4(uint32_t* r, uint32_t a) {
    asm volatile("ldmatrix.sync.aligned.m8n8.x4.shared.b16 {%0,%1,%2,%3}, [%4];"
        : "=r"(r[0]), "=r"(r[1]), "=r"(r[2]), "=r"(r[3]) : "r"(a));
}
__device__ __forceinline__ void ldsm4t(uint32_t* r, uint32_t a) {
    asm volatile("ldmatrix.sync.aligned.m8n8.x4.trans.shared.b16 {%0,%1,%2,%3}, [%4];"
        : "=r"(r[0]), "=r"(r[1]), "=r"(r[2]), "=r"(r[3]) : "r"(a));
}
__device__ __forceinline__ void mma16816(float* c, const uint32_t* a, const uint32_t* b) {
    asm volatile("mma.sync.aligned.m16n8k16.row.col.f32.bf16.bf16.f32 "
        "{%0,%1,%2,%3}, {%4,%5,%6,%7}, {%8,%9}, {%0,%1,%2,%3};"
        : "+f"(c[0]), "+f"(c[1]), "+f"(c[2]), "+f"(c[3])
        : "r"(a[0]), "r"(a[1]), "r"(a[2]), "r"(a[3]), "r"(b[0]), "r"(b[1]));
}
#define CP16(dst, src) asm volatile("cp.async.cg.shared.global [%0], [%1], 16;" :: "r"(dst), "l"(src))
#define CP_COMMIT()    asm volatile("cp.async.commit_group;" ::: "memory")
#define CP_WAIT1()     asm volatile("cp.async.wait_group 1;" ::: "memory")
#define CP_WAIT0()     asm volatile("cp.async.wait_group 0;" ::: "memory")

// ---- scratch ----
__device__ float g_q  [B_*N_*F_];
__device__ float g_xpp[KSPLIT*B_*E_*F_];
__device__ float g_kp [B_*E_*F_];
__device__ float g_vp [B_*E_*F_];
__device__ __nv_bfloat16 g_xh [B_*N_*F_], g_xl [B_*N_*F_];
__device__ __nv_bfloat16 g_aoh[B_*N_*F_], g_aol[B_*N_*F_];
__device__ __nv_bfloat16 g_xph[B_*E_*F_], g_xpl[B_*E_*F_];
__device__ __nv_bfloat16 g_ph [N_*E_],   g_pl [N_*E_];
__device__ __nv_bfloat16 g_wqh[F_*F_], g_wql[F_*F_];
__device__ __nv_bfloat16 g_wkh[F_*F_], g_wkl[F_*F_];
__device__ __nv_bfloat16 g_wvh[F_*F_], g_wvl[F_*F_];
__device__ __nv_bfloat16 g_woh[F_*F_], g_wol[F_*F_];

// ---------------------------------------------------------------------------
__global__ void __launch_bounds__(256)
split_bf16(const float* __restrict__ in, __nv_bfloat16* __restrict__ hi,
           __nv_bfloat16* __restrict__ lo, int n4)
{
    int i = blockIdx.x * 256 + threadIdx.x;
    if (i >= n4) return;
    float4 v = ((const float4*)in)[i];
    __nv_bfloat16 h0 = __float2bfloat16(v.x), h1 = __float2bfloat16(v.y);
    __nv_bfloat16 h2 = __float2bfloat16(v.z), h3 = __float2bfloat16(v.w);
    __nv_bfloat16 l0 = __float2bfloat16(v.x - __bfloat162float(h0));
    __nv_bfloat16 l1 = __float2bfloat16(v.y - __bfloat162float(h1));
    __nv_bfloat16 l2 = __float2bfloat16(v.z - __bfloat162float(h2));
    __nv_bfloat16 l3 = __float2bfloat16(v.w - __bfloat162float(h3));
    ((__nv_bfloat162*)hi)[i*2]   = __nv_bfloat162(h0, h1);
    ((__nv_bfloat162*)hi)[i*2+1] = __nv_bfloat162(h2, h3);
    ((__nv_bfloat162*)lo)[i*2]   = __nv_bfloat162(l0, l1);
    ((__nv_bfloat162*)lo)[i*2+1] = __nv_bfloat162(l2, l3);
}

// ---------------------------------------------------------------------------
// HMMA split-bf16 NT GEMM: C[m,n] = sum_k A[m,k]*B[n,k]; K = N = 1024.
// CTA 128x128, BK=32, 3-stage cp.async. z picks (B0,C0)/(B1,C1).
// ---------------------------------------------------------------------------
#define PAD        40
#define MAT_BYTES  (128 * PAD * 2)
#define STG_BYTES  (4 * MAT_BYTES)
#define TCG_SMEM   (3 * STG_BYTES)

__device__ __forceinline__ void stage_load(
    const __nv_bfloat16* __restrict__ Ah, const __nv_bfloat16* __restrict__ Al,
    const __nv_bfloat16* __restrict__ Bh, const __nv_bfloat16* __restrict__ Bl,
    int bm, int bn, int kt, uint32_t sbase, int tid)
{
    const __nv_bfloat16* gp[4] = {
        Ah + (size_t)bm * 1024, Al + (size_t)bm * 1024,
        Bh + (size_t)bn * 1024, Bl + (size_t)bn * 1024 };
#pragma unroll
    for (int m = 0; m < 4; m++) {
        const __nv_bfloat16* base = gp[m] + kt * 32;
        uint32_t sb = sbase + m * MAT_BYTES;
#pragma unroll
        for (int it = 0; it < 2; it++) {
            int c = tid + it * 256;
            int row = c >> 2, q = c & 3;
            CP16(sb + row * (PAD * 2) + q * 16, base + (size_t)row * 1024 + q * 8);
        }
    }
}

__global__ void __launch_bounds__(256, 1)
tc_gemm(const __nv_bfloat16* __restrict__ Ah, const __nv_bfloat16* __restrict__ Al,
        const __nv_bfloat16* __restrict__ Bh0, const __nv_bfloat16* __restrict__ Bl0,
        const __nv_bfloat16* __restrict__ Bh1, const __nv_bfloat16* __restrict__ Bl1,
        float* __restrict__ C0, float* __restrict__ C1)
{
    const __nv_bfloat16* Bh = blockIdx.z ? Bh1 : Bh0;
    const __nv_bfloat16* Bl = blockIdx.z ? Bl1 : Bl0;
    float*               C  = blockIdx.z ? C1  : C0;

    extern __shared__ __nv_bfloat16 smb[];
    const uint32_t sb = smem_u32(smb);
    const int tid  = threadIdx.x;
    const int lane = tid & 31;
    const int wid  = tid >> 5;
    const int bn   = blockIdx.x * 128;
    const int bm   = blockIdx.y * 128;
    const int wm   = (wid >> 2) * 64;
    const int wn   = (wid & 3) * 32;

    float acc[4][4][4];
#pragma unroll
    for (int i = 0; i < 4; i++)
#pragma unroll
        for (int j = 0; j < 4; j++)
#pragma unroll
            for (int v = 0; v < 4; v++) acc[i][j][v] = 0.f;

    const int lmA = lane & 15;
    const int lkA = (lane >> 4) * 16;
    const int rB  = (lane & 7) + ((lane >> 4) << 3);
    const int lkB = (((lane >> 3) & 1) << 3) * 2;

    stage_load(Ah, Al, Bh, Bl, bm, bn, 0, sb, tid);
    CP_COMMIT();
    stage_load(Ah, Al, Bh, Bl, bm, bn, 1, sb + STG_BYTES, tid);
    CP_COMMIT();

#pragma unroll 1
    for (int kt = 0; kt < 32; kt++) {
        if (kt + 2 < 32) { CP_WAIT1(); } else { CP_WAIT0(); }
        __syncthreads();
        if (kt + 2 < 32) {
            stage_load(Ah, Al, Bh, Bl, bm, bn, kt + 2,
                       sb + ((kt + 2) % 3) * STG_BYTES, tid);
            CP_COMMIT();
        }

        const uint32_t st = sb + (kt % 3) * STG_BYTES;
#pragma unroll
        for (int ks = 0; ks < 2; ks++) {
            uint32_t ah[4][4], al[4][4], bh[2][4], bl[2][4];
#pragma unroll
            for (int mt = 0; mt < 4; mt++) {
                uint32_t a = st + (wm + mt * 16 + lmA) * (PAD * 2) + lkA + ks * 32;
                ldsm4(ah[mt], a);
                ldsm4(al[mt], a + MAT_BYTES);
            }
#pragma unroll
            for (int p = 0; p < 2; p++) {
                uint32_t a = st + 2 * MAT_BYTES
                           + (wn + p * 16 + rB) * (PAD * 2) + lkB + ks * 32;
                ldsm4(bh[p], a);
                ldsm4(bl[p], a + MAT_BYTES);
            }
#pragma unroll
            for (int mt = 0; mt < 4; mt++)
#pragma unroll
                for (int nt = 0; nt < 4; nt++) {
                    float* cc = acc[mt][nt];
                    const uint32_t* bhp = &bh[nt >> 1][(nt & 1) * 2];
                    const uint32_t* blp = &bl[nt >> 1][(nt & 1) * 2];
                    mma16816(cc, ah[mt], bhp);
                    mma16816(cc, ah[mt], blp);
                    mma16816(cc, al[mt], bhp);
                }
        }
    }
    __syncthreads();

    const int mr = lane >> 2, nc = (lane & 3) * 2;
#pragma unroll
    for (int mt = 0; mt < 4; mt++)
#pragma unroll
        for (int nt = 0; nt < 4; nt++) {
            int m = bm + wm + mt * 16 + mr;
            int n = bn + wn + nt * 8 + nc;
            *(float2*)&C[(size_t)m * 1024 + n] =
                make_float2(acc[mt][nt][0], acc[mt][nt][1]);
            *(float2*)&C[(size_t)(m + 8) * 1024 + n] =
                make_float2(acc[mt][nt][2], acc[mt][nt][3]);
        }
}

// ---------------------------------------------------------------------------
// HMMA split-bf16 TN GEMM (trans ldmatrix): xp[b,e,f] = sum_n proj[n,e]*x[b,n,f]
// A = proj [n][e] (k=n rows), B = x [n][f]. CTA tile 128e x 128f, BK=32 n.
// Split-K x4 -> g_xpp. Row stride 272B => conflict-free trans ldmatrix.
// ---------------------------------------------------------------------------
#define PPAD       136                 // bf16 per smem row (272 B)
#define PT_BYTES   (32 * PPAD * 2)     // 8704
#define PSTG       (4 * PT_BYTES)      // 34816
#define PROJ_SMEM  (3 * PSTG)          // 104448

__device__ __forceinline__ void stage_load_p(
    const __nv_bfloat16* __restrict__ ph, const __nv_bfloat16* __restrict__ pl,
    const __nv_bfloat16* __restrict__ xh, const __nv_bfloat16* __restrict__ xl,
    int e0, int f0, int n0, uint32_t sbase, int tid)
{
    // tiles: [32 n-rows][128 cols]; proj gstride 256, x gstride 1024
    const __nv_bfloat16* gp[4] = {
        ph + (size_t)n0 * 256 + e0,  pl + (size_t)n0 * 256 + e0,
        xh + (size_t)n0 * 1024 + f0, xl + (size_t)n0 * 1024 + f0 };
    const int gs[4] = {256, 256, 1024, 1024};
#pragma unroll
    for (int m = 0; m < 4; m++) {
        uint32_t sb = sbase + m * PT_BYTES;
#pragma unroll
        for (int it = 0; it < 2; it++) {
            int c = tid + it * 256;
            int row = c >> 4, q = c & 15;
            CP16(sb + row * (PPAD * 2) + q * 16, gp[m] + (size_t)row * gs[m] + q * 8);
        }
    }
}

__global__ void __launch_bounds__(256, 1)
proj_tc(const __nv_bfloat16* __restrict__ ph, const __nv_bfloat16* __restrict__ pl,
        const __nv_bfloat16* __restrict__ xh, const __nv_bfloat16* __restrict__ xl)
{
    extern __shared__ __nv_bfloat16 smb[];
    const uint32_t sb = smem_u32(smb);
    const int tid  = threadIdx.x;
    const int lane = tid & 31;
    const int wid  = tid >> 5;
    const int f0   = blockIdx.x * 128;
    const int e0   = blockIdx.y * 128;
    const int b    = blockIdx.z >> 2;
    const int ksp  = blockIdx.z & 3;
    const int wm   = (wid >> 2) * 64;      // e within tile
    const int wn   = (wid & 3) * 32;       // f within tile
    const int nlo  = ksp * (N_ / KSPLIT);

    const __nv_bfloat16* xhb = xh + (size_t)b * N_ * F_;
    const __nv_bfloat16* xlb = xl + (size_t)b * N_ * F_;

    float acc[4][4][4];
#pragma unroll
    for (int i = 0; i < 4; i++)
#pragma unroll
        for (int j = 0; j < 4; j++)
#pragma unroll
            for (int v = 0; v < 4; v++) acc[i][j][v] = 0.f;

    // trans ldmatrix lane maps (k = n rows)
    const int krA = (lane & 7) + ((lane & 16) >> 1);   // A: k row
    const int mcA = lane & 8;                           // A: +m col
    const int krB = (lane & 7) + (lane & 8);            // B: k row
    const int fcB = (lane >> 4) << 3;                   // B: +f col

    stage_load_p(ph, pl, xhb, xlb, e0, f0, nlo + 0,  sb,            tid);
    CP_COMMIT();
    stage_load_p(ph, pl, xhb, xlb, e0, f0, nlo + 32, sb + PSTG,     tid);
    CP_COMMIT();

#pragma unroll 1
    for (int kt = 0; kt < 32; kt++) {
        if (kt + 2 < 32) { CP_WAIT1(); } else { CP_WAIT0(); }
        __syncthreads();
        if (kt + 2 < 32) {
            stage_load_p(ph, pl, xhb, xlb, e0, f0, nlo + (kt + 2) * 32,
                         sb + ((kt + 2) % 3) * PSTG, tid);
            CP_COMMIT();
        }

        const uint32_t st = sb + (kt % 3) * PSTG;
#pragma unroll
        for (int ks = 0; ks < 2; ks++) {
            uint32_t ah[4][4], al[4][4], bh[2][4], bl[2][4];
#pragma unroll
            for (int mt = 0; mt < 4; mt++) {
                uint32_t a = st + (ks * 16 + krA) * (PPAD * 2)
                           + (wm + mt * 16 + mcA) * 2;
                ldsm4t(ah[mt], a);
                ldsm4t(al[mt], a + PT_BYTES);
            }
#pragma unroll
            for (int p = 0; p < 2; p++) {
                uint32_t a = st + 2 * PT_BYTES + (ks * 16 + krB) * (PPAD * 2)
                           + (wn + p * 16 + fcB) * 2;
                ldsm4t(bh[p], a);
                ldsm4t(bl[p], a + PT_BYTES);
            }
#pragma unroll
            for (int mt = 0; mt < 4; mt++)
#pragma unroll
                for (int nt = 0; nt < 4; nt++) {
                    float* cc = acc[mt][nt];
                    const uint32_t* bhp = &bh[nt >> 1][(nt & 1) * 2];
                    const uint32_t* blp = &bl[nt >> 1][(nt & 1) * 2];
                    mma16816(cc, ah[mt], bhp);
                    mma16816(cc, ah[mt], blp);
                    mma16816(cc, al[mt], bhp);
                }
        }
    }
    __syncthreads();

    float* Cb = g_xpp + (size_t)ksp * (B_ * E_ * F_) + (size_t)b * E_ * F_;
    const int mr = lane >> 2, nc = (lane & 3) * 2;
#pragma unroll
    for (int mt = 0; mt < 4; mt++)
#pragma unroll
        for (int nt = 0; nt < 4; nt++) {
            int e = e0 + wm + mt * 16 + mr;
            int f = f0 + wn + nt * 8 + nc;
            *(float2*)&Cb[(size_t)e * F_ + f] =
                make_float2(acc[mt][nt][0], acc[mt][nt][1]);
            *(float2*)&Cb[(size_t)(e + 8) * F_ + f] =
                make_float2(acc[mt][nt][2], acc[mt][nt][3]);
        }
}

// reduce split-K partials; emit xp as split bf16 hi/lo (input for Kp/Vp GEMM)
__global__ void __launch_bounds__(256)
xp_reduce()
{
    int i = blockIdx.x * 256 + threadIdx.x;
    const int tot = B_ * E_ * F_ / 4;
    if (i >= tot) return;
    const float4* p0 = (const float4*)g_xpp;
    float4 a = p0[i], b = p0[i + tot], c = p0[i + 2 * tot], d = p0[i + 3 * tot];
    float s[4] = {a.x + b.x + c.x + d.x, a.y + b.y + c.y + d.y,
                  a.z + b.z + c.z + d.z, a.w + b.w + c.w + d.w};
    __nv_bfloat16 h[4], l[4];
#pragma unroll
    for (int k = 0; k < 4; k++) {
        h[k] = __float2bfloat16(s[k]);
        l[k] = __float2bfloat16(s[k] - __bfloat162float(h[k]));
    }
    ((__nv_bfloat162*)g_xph)[i*2]   = __nv_bfloat162(h[0], h[1]);
    ((__nv_bfloat162*)g_xph)[i*2+1] = __nv_bfloat162(h[2], h[3]);
    ((__nv_bfloat162*)g_xpl)[i*2]   = __nv_bfloat162(l[0], l[1]);
    ((__nv_bfloat162*)g_xpl)[i*2+1] = __nv_bfloat162(l[2], l[3]);
}

// ---------------------------------------------------------------------------
// Persistent fused attention, 512 threads (16 warps x 4 queries), FFMA2.
// ---------------------------------------------------------------------------
__global__ void __launch_bounds__(512, 1)
attn_kernel()
{
    extern __shared__ float sm[];
    float* Ks = sm;
    float* Vs = Ks + 64 * E_;
    float* Qw = Vs + E_ * 64;
    float* Sw = Qw + 16 * 4 * 64;

    const int h  = blockIdx.y;
    const int b  = blockIdx.z;
    const int tid  = threadIdx.x;
    const int lane = tid & 31;
    const int w    = tid >> 5;

    const float* kpb = g_kp + (size_t)b * E_ * F_ + h * D_;
    const float* vpb = g_vp + (size_t)b * E_ * F_ + h * D_;

    for (int idx = tid; idx < E_ * 16; idx += 512) {
        int e = idx >> 4, d4 = (idx & 15) << 2;
        float4 v = *(const float4*)(kpb + (size_t)e * F_ + d4);
        Ks[(d4 + 0) * E_ + e] = v.x;
        Ks[(d4 + 1) * E_ + e] = v.y;
        Ks[(d4 + 2) * E_ + e] = v.z;
        Ks[(d4 + 3) * E_ + e] = v.w;
        float4 u = *(const float4*)(vpb + (size_t)e * F_ + d4);
        *(float4*)(Vs + e * 64 + d4) = u;
    }
    __syncthreads();

    float* Qm = Qw + w * 4 * 64;
    float* Sm = Sw + w * 4 * 256;
    const int d0 = lane * 2;
    const int ea = lane * 4;
    const int eb = 128 + lane * 4;

    for (int t = blockIdx.x; t < N_ / 64; t += SPLIT) {
        const int n0 = t * 64 + w * 4;
        const float* qp = g_q + (size_t)(b * N_ + n0) * F_ + h * D_;

#pragma unroll
        for (int s = 0; s < 2; s++) {
            int idx = s * 32 + lane;
            int r = idx >> 4, c = (idx & 15) * 4;
            float4 v = *(const float4*)(qp + (size_t)r * F_ + c);
            *(float4*)(Qm + r * 64 + c) =
                make_float4(v.x * 0.125f, v.y * 0.125f, v.z * 0.125f, v.w * 0.125f);
        }
        __syncwarp();

        ull c2[4][4];
#pragma unroll
        for (int i = 0; i < 4; i++)
#pragma unroll
            for (int jp = 0; jp < 4; jp++) c2[i][jp] = 0ull;

        for (int dc = 0; dc < 64; dc += 4) {
            ull ka[4][2], kb[4][2];
#pragma unroll
            for (int dd = 0; dd < 4; dd++) {
                ulonglong2 t0 = *(const ulonglong2*)&Ks[(dc + dd) * E_ + ea];
                ulonglong2 t1 = *(const ulonglong2*)&Ks[(dc + dd) * E_ + eb];
                ka[dd][0] = t0.x; ka[dd][1] = t0.y;
                kb[dd][0] = t1.x; kb[dd][1] = t1.y;
            }
#pragma unroll
            for (int i = 0; i < 4; i++) {
                float4 q = *(const float4*)&Qm[i * 64 + dc];
                float qa[4] = {q.x, q.y, q.z, q.w};
#pragma unroll
                for (int dd = 0; dd < 4; dd++) {
                    ull qd = dup2(qa[dd]);
                    fma2(c2[i][0], qd, ka[dd][0]);
                    fma2(c2[i][1], qd, ka[dd][1]);
                    fma2(c2[i][2], qd, kb[dd][0]);
                    fma2(c2[i][3], qd, kb[dd][1]);
                }
            }
        }

#pragma unroll
        for (int i = 0; i < 4; i++) {
            float2 v0 = upk(c2[i][0]), v1 = upk(c2[i][1]);
            float2 v2 = upk(c2[i][2]), v3 = upk(c2[i][3]);
            float va[8] = {v0.x, v0.y, v1.x, v1.y, v2.x, v2.y, v3.x, v3.y};
            float m = va[0];
#pragma unroll
            for (int j = 1; j < 8; j++) m = fmaxf(m, va[j]);
#pragma unroll
            for (int o = 16; o > 0; o >>= 1)
                m = fmaxf(m, __shfl_xor_sync(0xffffffffu, m, o));
            float s = 0.f;
#pragma unroll
            for (int j = 0; j < 8; j++) { va[j] = __expf(va[j] - m); s += va[j]; }
#pragma unroll
            for (int o = 16; o > 0; o >>= 1)
                s += __shfl_xor_sync(0xffffffffu, s, o);
            float inv = 1.f / s;
#pragma unroll
            for (int j = 0; j < 8; j++) va[j] *= inv;
            *(float4*)&Sm[i * E_ + ea] = make_float4(va[0], va[1], va[2], va[3]);
            *(float4*)&Sm[i * E_ + eb] = make_float4(va[4], va[5], va[6], va[7]);
        }
        __syncwarp();

        ull acc[4];
#pragma unroll
        for (int i = 0; i < 4; i++) acc[i] = 0ull;

        for (int e = 0; e < E_; e += 4) {
            ull vv[4];
#pragma unroll
            for (int k4 = 0; k4 < 4; k4++)
                vv[k4] = *(const ull*)&Vs[(e + k4) * 64 + d0];
#pragma unroll
            for (int i = 0; i < 4; i++) {
                float4 aa = *(const float4*)&Sm[i * E_ + e];
                fma2(acc[i], dup2(aa.x), vv[0]);
                fma2(acc[i], dup2(aa.y), vv[1]);
                fma2(acc[i], dup2(aa.z), vv[2]);
                fma2(acc[i], dup2(aa.w), vv[3]);
            }
        }

        const size_t obase = (size_t)(b * N_ + n0) * F_ + h * D_ + d0;
#pragma unroll
        for (int i = 0; i < 4; i++) {
            float2 o = upk(acc[i]);
            __nv_bfloat16 hx = __float2bfloat16(o.x);
            __nv_bfloat16 hy = __float2bfloat16(o.y);
            __nv_bfloat16 lx = __float2bfloat16(o.x - __bfloat162float(hx));
            __nv_bfloat16 ly = __float2bfloat16(o.y - __bfloat162float(hy));
            size_t p = obase + (size_t)i * F_;
            *(__nv_bfloat162*)(g_aoh + p) = __nv_bfloat162(hx, hy);
            *(__nv_bfloat162*)(g_aol + p) = __nv_bfloat162(lx, ly);
        }
    }
}

// ---------------------------------------------------------------------------
extern "C" void kernel_launch(void* const* d_in, const int* in_sizes, int n_in,
                              void* d_out, int out_size)
{
    (void)in_sizes; (void)n_in; (void)out_size;
    const float* x    = (const float*)d_in[0];
    const float* proj = (const float*)d_in[1];
    const float* Wq   = (const float*)d_in[2];
    const float* Wk   = (const float*)d_in[3];
    const float* Wv   = (const float*)d_in[4];
    const float* Wo   = (const float*)d_in[5];
    float* out = (float*)d_out;

    float *pq, *pkp, *pvp;
    cudaGetSymbolAddress((void**)&pq,  g_q);
    cudaGetSymbolAddress((void**)&pkp, g_kp);
    cudaGetSymbolAddress((void**)&pvp, g_vp);
    __nv_bfloat16 *xh, *xl, *aoh, *aol, *xph, *xpl, *ph, *pl;
    __nv_bfloat16 *wqh, *wql, *wkh, *wkl, *wvh, *wvl, *woh, *wol;
    cudaGetSymbolAddress((void**)&xh,  g_xh);
    cudaGetSymbolAddress((void**)&xl,  g_xl);
    cudaGetSymbolAddress((void**)&aoh, g_aoh);
    cudaGetSymbolAddress((void**)&aol, g_aol);
    cudaGetSymbolAddress((void**)&xph, g_xph);
    cudaGetSymbolAddress((void**)&xpl, g_xpl);
    cudaGetSymbolAddress((void**)&ph,  g_ph);
    cudaGetSymbolAddress((void**)&pl,  g_pl);
    cudaGetSymbolAddress((void**)&wqh, g_wqh);
    cudaGetSymbolAddress((void**)&wql, g_wql);
    cudaGetSymbolAddress((void**)&wkh, g_wkh);
    cudaGetSymbolAddress((void**)&wkl, g_wkl);
    cudaGetSymbolAddress((void**)&wvh, g_wvh);
    cudaGetSymbolAddress((void**)&wvl, g_wvl);
    cudaGetSymbolAddress((void**)&woh, g_woh);
    cudaGetSymbolAddress((void**)&wol, g_wol);

    const size_t ATT_SMEM =
        (size_t)(64 * E_ + E_ * 64 + 16 * 4 * 64 + 16 * 4 * E_) * sizeof(float);
    cudaFuncSetAttribute(attn_kernel,
                         cudaFuncAttributeMaxDynamicSharedMemorySize, (int)ATT_SMEM);
    cudaFuncSetAttribute(tc_gemm,
                         cudaFuncAttributeMaxDynamicSharedMemorySize, TCG_SMEM);
    cudaFuncSetAttribute(proj_tc,
                         cudaFuncAttributeMaxDynamicSharedMemorySize, PROJ_SMEM);

    // 0) splits
    split_bf16<<<(B_*N_*F_/4 + 255)/256, 256>>>(x,    xh,  xl,  B_*N_*F_/4);
    split_bf16<<<(N_*E_/4   + 255)/256, 256>>>(proj, ph,  pl,  N_*E_/4);
    split_bf16<<<(F_*F_/4   + 255)/256, 256>>>(Wq,   wqh, wql, F_*F_/4);
    split_bf16<<<(F_*F_/4   + 255)/256, 256>>>(Wk,   wkh, wkl, F_*F_/4);
    split_bf16<<<(F_*F_/4   + 255)/256, 256>>>(Wv,   wvh, wvl, F_*F_/4);
    split_bf16<<<(F_*F_/4   + 255)/256, 256>>>(Wo,   woh, wol, F_*F_/4);
    // 1) xp = proj^T @ x (HMMA, split-K x4) + reduce (emits bf16 hi/lo)
    proj_tc<<<dim3(8, 2, B_ * KSPLIT), 256, PROJ_SMEM>>>(ph, pl, xh, xl);
    xp_reduce<<<(B_*E_*F_/4 + 255)/256, 256>>>();
    // 2) Kp = xp @ Wk^T ; Vp = xp @ Wv^T (HMMA, one launch via z)
    tc_gemm<<<dim3(8, 8, 2), 256, TCG_SMEM>>>(xph, xpl, wkh, wkl, wvh, wvl, pkp, pvp);
    // 3) Q = x @ Wq^T (HMMA)
    tc_gemm<<<dim3(8, 128, 1), 256, TCG_SMEM>>>(xh, xl, wqh, wql, wqh, wql, pq, pq);
    // 4) fused persistent attention -> ao (hi/lo bf16)
    attn_kernel<<<dim3(SPLIT, H_, B_), 512, ATT_SMEM>>>();
    // 5) out = ao @ Wo^T (HMMA)
    tc_gemm<<<dim3(8, 128, 1), 256, TCG_SMEM>>>(aoh, aol, woh, wol, woh, wol, out, out);
}

// round 8
// speedup vs baseline: 3.1138x; 1.2818x over previous
#include <cuda_runtime.h>
#include <cuda_bf16.h>
#include <cstdint>

#define B_ 4
#define N_ 4096
#define F_ 1024
#define H_ 16
#define D_ 64
#define E_ 256
#define KSPLIT 4

// ---- tensor-core helpers (portable sm_80+) ----
__device__ __forceinline__ uint32_t smem_u32(const void* p) {
    uint32_t a;
    asm("{ .reg .u64 t; cvta.to.shared.u64 t, %1; cvt.u32.u64 %0, t; }" : "=r"(a) : "l"(p));
    return a;
}
__device__ __forceinline__ void ldsm4(uint32_t* r, uint32_t a) {
    asm volatile("ldmatrix.sync.aligned.m8n8.x4.shared.b16 {%0,%1,%2,%3}, [%4];"
        : "=r"(r[0]), "=r"(r[1]), "=r"(r[2]), "=r"(r[3]) : "r"(a));
}
__device__ __forceinline__ void ldsm4t(uint32_t* r, uint32_t a) {
    asm volatile("ldmatrix.sync.aligned.m8n8.x4.trans.shared.b16 {%0,%1,%2,%3}, [%4];"
        : "=r"(r[0]), "=r"(r[1]), "=r"(r[2]), "=r"(r[3]) : "r"(a));
}
__device__ __forceinline__ void mma16816(float* c, const uint32_t* a, const uint32_t* b) {
    asm volatile("mma.sync.aligned.m16n8k16.row.col.f32.bf16.bf16.f32 "
        "{%0,%1,%2,%3}, {%4,%5,%6,%7}, {%8,%9}, {%0,%1,%2,%3};"
        : "+f"(c[0]), "+f"(c[1]), "+f"(c[2]), "+f"(c[3])
        : "r"(a[0]), "r"(a[1]), "r"(a[2]), "r"(a[3]), "r"(b[0]), "r"(b[1]));
}
#define CP16(dst, src) asm volatile("cp.async.cg.shared.global [%0], [%1], 16;" :: "r"(dst), "l"(src))
#define CP_COMMIT()    asm volatile("cp.async.commit_group;" ::: "memory")
#define CP_WAIT1()     asm volatile("cp.async.wait_group 1;" ::: "memory")
#define CP_WAIT0()     asm volatile("cp.async.wait_group 0;" ::: "memory")

__device__ __forceinline__ void split1(float v, __nv_bfloat16& h, __nv_bfloat16& l) {
    h = __float2bfloat16(v);
    l = __float2bfloat16(v - __bfloat162float(h));
}
__device__ __forceinline__ uint32_t packbf(float a, float b) {
    __nv_bfloat162 t(__float2bfloat16(a), __float2bfloat16(b));
    return *(uint32_t*)&t;
}
__device__ __forceinline__ uint32_t packbf_lo(float a, float b) {
    __nv_bfloat16 ha = __float2bfloat16(a), hb = __float2bfloat16(b);
    __nv_bfloat162 t(__float2bfloat16(a - __bfloat162float(ha)),
                     __float2bfloat16(b - __bfloat162float(hb)));
    return *(uint32_t*)&t;
}

// ---- scratch ----
__device__ float g_xpp[KSPLIT*B_*E_*F_];
__device__ __nv_bfloat16 g_xh [B_*N_*F_], g_xl [B_*N_*F_];
__device__ __nv_bfloat16 g_qh [B_*N_*F_], g_ql [B_*N_*F_];
__device__ __nv_bfloat16 g_aoh[B_*N_*F_], g_aol[B_*N_*F_];
__device__ __nv_bfloat16 g_xph[B_*E_*F_], g_xpl[B_*E_*F_];
__device__ __nv_bfloat16 g_kph[B_*E_*F_], g_kpl[B_*E_*F_];
__device__ __nv_bfloat16 g_vth[B_*F_*E_], g_vtl[B_*F_*E_];
__device__ __nv_bfloat16 g_ph [N_*E_],   g_pl [N_*E_];
__device__ __nv_bfloat16 g_wqh[F_*F_], g_wql[F_*F_];
__device__ __nv_bfloat16 g_wkh[F_*F_], g_wkl[F_*F_];
__device__ __nv_bfloat16 g_wvh[F_*F_], g_wvl[F_*F_];
__device__ __nv_bfloat16 g_woh[F_*F_], g_wol[F_*F_];

// ---------------------------------------------------------------------------
__global__ void __launch_bounds__(256)
split_bf16(const float* __restrict__ in, __nv_bfloat16* __restrict__ hi,
           __nv_bfloat16* __restrict__ lo, int n4)
{
    int i = blockIdx.x * 256 + threadIdx.x;
    if (i >= n4) return;
    float4 v = ((const float4*)in)[i];
    __nv_bfloat16 h0, h1, h2, h3, l0, l1, l2, l3;
    split1(v.x, h0, l0); split1(v.y, h1, l1);
    split1(v.z, h2, l2); split1(v.w, h3, l3);
    ((__nv_bfloat162*)hi)[i*2]   = __nv_bfloat162(h0, h1);
    ((__nv_bfloat162*)hi)[i*2+1] = __nv_bfloat162(h2, h3);
    ((__nv_bfloat162*)lo)[i*2]   = __nv_bfloat162(l0, l1);
    ((__nv_bfloat162*)lo)[i*2+1] = __nv_bfloat162(l2, l3);
}

// ---------------------------------------------------------------------------
// HMMA split-bf16 NT GEMM. C = A·B^T, K=N=1024. CTA 128x128, BK=32, 3-stage.
// Epilogue modes: 0 = f32; 1 = split bf16 (scaled); 2 = split bf16;
//                 3 = split bf16 transposed per-batch (b = m>>8, e = m&255).
// ---------------------------------------------------------------------------
#define PAD        40
#define MAT_BYTES  (128 * PAD * 2)
#define STG_BYTES  (4 * MAT_BYTES)
#define TCG_SMEM   (3 * STG_BYTES)

__device__ __forceinline__ void stage_load(
    const __nv_bfloat16* __restrict__ Ah, const __nv_bfloat16* __restrict__ Al,
    const __nv_bfloat16* __restrict__ Bh, const __nv_bfloat16* __restrict__ Bl,
    int bm, int bn, int kt, uint32_t sbase, int tid)
{
    const __nv_bfloat16* gp[4] = {
        Ah + (size_t)bm * 1024, Al + (size_t)bm * 1024,
        Bh + (size_t)bn * 1024, Bl + (size_t)bn * 1024 };
#pragma unroll
    for (int m = 0; m < 4; m++) {
        const __nv_bfloat16* base = gp[m] + kt * 32;
        uint32_t sb = sbase + m * MAT_BYTES;
#pragma unroll
        for (int it = 0; it < 2; it++) {
            int c = tid + it * 256;
            int row = c >> 2, q = c & 3;
            CP16(sb + row * (PAD * 2) + q * 16, base + (size_t)row * 1024 + q * 8);
        }
    }
}

__global__ void __launch_bounds__(256, 1)
tc_gemm(const __nv_bfloat16* __restrict__ Ah, const __nv_bfloat16* __restrict__ Al,
        const __nv_bfloat16* __restrict__ Bh0, const __nv_bfloat16* __restrict__ Bl0,
        const __nv_bfloat16* __restrict__ Bh1, const __nv_bfloat16* __restrict__ Bl1,
        float* Cf0, float* Cf1,
        __nv_bfloat16* Ch0, __nv_bfloat16* Cl0,
        __nv_bfloat16* Ch1, __nv_bfloat16* Cl1,
        int mode0, int mode1, float scale)
{
    const __nv_bfloat16* Bh = blockIdx.z ? Bh1 : Bh0;
    const __nv_bfloat16* Bl = blockIdx.z ? Bl1 : Bl0;
    float*         Cf = blockIdx.z ? Cf1 : Cf0;
    __nv_bfloat16* Ch = blockIdx.z ? Ch1 : Ch0;
    __nv_bfloat16* Cl = blockIdx.z ? Cl1 : Cl0;
    const int mode = blockIdx.z ? mode1 : mode0;

    extern __shared__ __nv_bfloat16 smb[];
    const uint32_t sb = smem_u32(smb);
    const int tid  = threadIdx.x;
    const int lane = tid & 31;
    const int wid  = tid >> 5;
    const int bn   = blockIdx.x * 128;
    const int bm   = blockIdx.y * 128;
    const int wm   = (wid >> 2) * 64;
    const int wn   = (wid & 3) * 32;

    float acc[4][4][4];
#pragma unroll
    for (int i = 0; i < 4; i++)
#pragma unroll
        for (int j = 0; j < 4; j++)
#pragma unroll
            for (int v = 0; v < 4; v++) acc[i][j][v] = 0.f;

    const int lmA = lane & 15;
    const int lkA = (lane >> 4) * 16;
    const int rB  = (lane & 7) + ((lane >> 4) << 3);
    const int lkB = ((lane >> 3) & 1) * 16;

    stage_load(Ah, Al, Bh, Bl, bm, bn, 0, sb, tid);
    CP_COMMIT();
    stage_load(Ah, Al, Bh, Bl, bm, bn, 1, sb + STG_BYTES, tid);
    CP_COMMIT();

#pragma unroll 1
    for (int kt = 0; kt < 32; kt++) {
        if (kt + 2 < 32) { CP_WAIT1(); } else { CP_WAIT0(); }
        __syncthreads();
        if (kt + 2 < 32) {
            stage_load(Ah, Al, Bh, Bl, bm, bn, kt + 2,
                       sb + ((kt + 2) % 3) * STG_BYTES, tid);
            CP_COMMIT();
        }

        const uint32_t st = sb + (kt % 3) * STG_BYTES;
#pragma unroll
        for (int ks = 0; ks < 2; ks++) {
            uint32_t ah[4][4], al[4][4], bh[2][4], bl[2][4];
#pragma unroll
            for (int mt = 0; mt < 4; mt++) {
                uint32_t a = st + (wm + mt * 16 + lmA) * (PAD * 2) + lkA + ks * 32;
                ldsm4(ah[mt], a);
                ldsm4(al[mt], a + MAT_BYTES);
            }
#pragma unroll
            for (int p = 0; p < 2; p++) {
                uint32_t a = st + 2 * MAT_BYTES
                           + (wn + p * 16 + rB) * (PAD * 2) + lkB + ks * 32;
                ldsm4(bh[p], a);
                ldsm4(bl[p], a + MAT_BYTES);
            }
#pragma unroll
            for (int mt = 0; mt < 4; mt++)
#pragma unroll
                for (int nt = 0; nt < 4; nt++) {
                    float* cc = acc[mt][nt];
                    const uint32_t* bhp = &bh[nt >> 1][(nt & 1) * 2];
                    const uint32_t* blp = &bl[nt >> 1][(nt & 1) * 2];
                    mma16816(cc, ah[mt], bhp);
                    mma16816(cc, ah[mt], blp);
                    mma16816(cc, al[mt], bhp);
                }
        }
    }
    __syncthreads();

    const int mr = lane >> 2, nc = (lane & 3) * 2;
#pragma unroll
    for (int mt = 0; mt < 4; mt++)
#pragma unroll
        for (int nt = 0; nt < 4; nt++) {
            int m = bm + wm + mt * 16 + mr;
            int n = bn + wn + nt * 8 + nc;
            float v00 = acc[mt][nt][0], v01 = acc[mt][nt][1];
            float v10 = acc[mt][nt][2], v11 = acc[mt][nt][3];
            if (mode == 0) {
                *(float2*)&Cf[(size_t)m * 1024 + n]       = make_float2(v00, v01);
                *(float2*)&Cf[(size_t)(m + 8) * 1024 + n] = make_float2(v10, v11);
            } else if (mode == 3) {
                int b = m >> 8, e = m & 255;
                __nv_bfloat16 h, l;
                split1(v00, h, l);
                Ch[(size_t)b*F_*E_ + (size_t)n*E_ + e] = h;
                Cl[(size_t)b*F_*E_ + (size_t)n*E_ + e] = l;
                split1(v01, h, l);
                Ch[(size_t)b*F_*E_ + (size_t)(n+1)*E_ + e] = h;
                Cl[(size_t)b*F_*E_ + (size_t)(n+1)*E_ + e] = l;
                split1(v10, h, l);
                Ch[(size_t)b*F_*E_ + (size_t)n*E_ + e + 8] = h;
                Cl[(size_t)b*F_*E_ + (size_t)n*E_ + e + 8] = l;
                split1(v11, h, l);
                Ch[(size_t)b*F_*E_ + (size_t)(n+1)*E_ + e + 8] = h;
                Cl[(size_t)b*F_*E_ + (size_t)(n+1)*E_ + e + 8] = l;
            } else {
                float s = (mode == 1) ? scale : 1.f;
                v00 *= s; v01 *= s; v10 *= s; v11 *= s;
                __nv_bfloat16 h0, l0, h1, l1;
                split1(v00, h0, l0); split1(v01, h1, l1);
                *(__nv_bfloat162*)&Ch[(size_t)m*1024 + n] = __nv_bfloat162(h0, h1);
                *(__nv_bfloat162*)&Cl[(size_t)m*1024 + n] = __nv_bfloat162(l0, l1);
                split1(v10, h0, l0); split1(v11, h1, l1);
                *(__nv_bfloat162*)&Ch[(size_t)(m+8)*1024 + n] = __nv_bfloat162(h0, h1);
                *(__nv_bfloat162*)&Cl[(size_t)(m+8)*1024 + n] = __nv_bfloat162(l0, l1);
            }
        }
}

// ---------------------------------------------------------------------------
// HMMA split-bf16 TN GEMM (trans ldmatrix): xp = proj^T @ x, split-K x4.
// ---------------------------------------------------------------------------
#define PPAD       136
#define PT_BYTES   (32 * PPAD * 2)
#define PSTG       (4 * PT_BYTES)
#define PROJ_SMEM  (3 * PSTG)

__device__ __forceinline__ void stage_load_p(
    const __nv_bfloat16* __restrict__ ph, const __nv_bfloat16* __restrict__ pl,
    const __nv_bfloat16* __restrict__ xh, const __nv_bfloat16* __restrict__ xl,
    int e0, int f0, int n0, uint32_t sbase, int tid)
{
    const __nv_bfloat16* gp[4] = {
        ph + (size_t)n0 * 256 + e0,  pl + (size_t)n0 * 256 + e0,
        xh + (size_t)n0 * 1024 + f0, xl + (size_t)n0 * 1024 + f0 };
    const int gs[4] = {256, 256, 1024, 1024};
#pragma unroll
    for (int m = 0; m < 4; m++) {
        uint32_t sb = sbase + m * PT_BYTES;
#pragma unroll
        for (int it = 0; it < 2; it++) {
            int c = tid + it * 256;
            int row = c >> 4, q = c & 15;
            CP16(sb + row * (PPAD * 2) + q * 16, gp[m] + (size_t)row * gs[m] + q * 8);
        }
    }
}

__global__ void __launch_bounds__(256, 1)
proj_tc(const __nv_bfloat16* __restrict__ ph, const __nv_bfloat16* __restrict__ pl,
        const __nv_bfloat16* __restrict__ xh, const __nv_bfloat16* __restrict__ xl)
{
    extern __shared__ __nv_bfloat16 smb[];
    const uint32_t sb = smem_u32(smb);
    const int tid  = threadIdx.x;
    const int lane = tid & 31;
    const int wid  = tid >> 5;
    const int f0   = blockIdx.x * 128;
    const int e0   = blockIdx.y * 128;
    const int b    = blockIdx.z >> 2;
    const int ksp  = blockIdx.z & 3;
    const int wm   = (wid >> 2) * 64;
    const int wn   = (wid & 3) * 32;
    const int nlo  = ksp * (N_ / KSPLIT);

    const __nv_bfloat16* xhb = xh + (size_t)b * N_ * F_;
    const __nv_bfloat16* xlb = xl + (size_t)b * N_ * F_;

    float acc[4][4][4];
#pragma unroll
    for (int i = 0; i < 4; i++)
#pragma unroll
        for (int j = 0; j < 4; j++)
#pragma unroll
            for (int v = 0; v < 4; v++) acc[i][j][v] = 0.f;

    const int krA = (lane & 7) + ((lane & 16) >> 1);
    const int mcA = lane & 8;
    const int krB = (lane & 7) + (lane & 8);
    const int fcB = (lane >> 4) << 3;

    stage_load_p(ph, pl, xhb, xlb, e0, f0, nlo + 0,  sb,        tid);
    CP_COMMIT();
    stage_load_p(ph, pl, xhb, xlb, e0, f0, nlo + 32, sb + PSTG, tid);
    CP_COMMIT();

#pragma unroll 1
    for (int kt = 0; kt < 32; kt++) {
        if (kt + 2 < 32) { CP_WAIT1(); } else { CP_WAIT0(); }
        __syncthreads();
        if (kt + 2 < 32) {
            stage_load_p(ph, pl, xhb, xlb, e0, f0, nlo + (kt + 2) * 32,
                         sb + ((kt + 2) % 3) * PSTG, tid);
            CP_COMMIT();
        }

        const uint32_t st = sb + (kt % 3) * PSTG;
#pragma unroll
        for (int ks = 0; ks < 2; ks++) {
            uint32_t ah[4][4], al[4][4], bh[2][4], bl[2][4];
#pragma unroll
            for (int mt = 0; mt < 4; mt++) {
                uint32_t a = st + (ks * 16 + krA) * (PPAD * 2)
                           + (wm + mt * 16 + mcA) * 2;
                ldsm4t(ah[mt], a);
                ldsm4t(al[mt], a + PT_BYTES);
            }
#pragma unroll
            for (int p = 0; p < 2; p++) {
                uint32_t a = st + 2 * PT_BYTES + (ks * 16 + krB) * (PPAD * 2)
                           + (wn + p * 16 + fcB) * 2;
                ldsm4t(bh[p], a);
                ldsm4t(bl[p], a + PT_BYTES);
            }
#pragma unroll
            for (int mt = 0; mt < 4; mt++)
#pragma unroll
                for (int nt = 0; nt < 4; nt++) {
                    float* cc = acc[mt][nt];
                    const uint32_t* bhp = &bh[nt >> 1][(nt & 1) * 2];
                    const uint32_t* blp = &bl[nt >> 1][(nt & 1) * 2];
                    mma16816(cc, ah[mt], bhp);
                    mma16816(cc, ah[mt], blp);
                    mma16816(cc, al[mt], bhp);
                }
        }
    }
    __syncthreads();

    float* Cb = g_xpp + (size_t)ksp * (B_ * E_ * F_) + (size_t)b * E_ * F_;
    const int mr = lane >> 2, nc = (lane & 3) * 2;
#pragma unroll
    for (int mt = 0; mt < 4; mt++)
#pragma unroll
        for (int nt = 0; nt < 4; nt++) {
            int e = e0 + wm + mt * 16 + mr;
            int f = f0 + wn + nt * 8 + nc;
            *(float2*)&Cb[(size_t)e * F_ + f] =
                make_float2(acc[mt][nt][0], acc[mt][nt][1]);
            *(float2*)&Cb[(size_t)(e + 8) * F_ + f] =
                make_float2(acc[mt][nt][2], acc[mt][nt][3]);
        }
}

__global__ void __launch_bounds__(256)
xp_reduce()
{
    int i = blockIdx.x * 256 + threadIdx.x;
    const int tot = B_ * E_ * F_ / 4;
    if (i >= tot) return;
    const float4* p0 = (const float4*)g_xpp;
    float4 a = p0[i], b = p0[i + tot], c = p0[i + 2 * tot], d = p0[i + 3 * tot];
    float s[4] = {a.x + b.x + c.x + d.x, a.y + b.y + c.y + d.y,
                  a.z + b.z + c.z + d.z, a.w + b.w + c.w + d.w};
    __nv_bfloat16 h[4], l[4];
#pragma unroll
    for (int k = 0; k < 4; k++) split1(s[k], h[k], l[k]);
    ((__nv_bfloat162*)g_xph)[i*2]   = __nv_bfloat162(h[0], h[1]);
    ((__nv_bfloat162*)g_xph)[i*2+1] = __nv_bfloat162(h[2], h[3]);
    ((__nv_bfloat162*)g_xpl)[i*2]   = __nv_bfloat162(l[0], l[1]);
    ((__nv_bfloat162*)g_xpl)[i*2+1] = __nv_bfloat162(l[2], l[3]);
}

// ---------------------------------------------------------------------------
// HMMA flash-style attention. grid (N/128, H, B) = 2048 CTAs, 256 thr.
// Per CTA: 128 queries x one (b,h). Warp owns 16 query rows.
// S = Q·K^T (3-product split, Q pre-scaled); softmax unnormalized in regs;
// P split to bf16 hi/lo in-register (fragment reuse); AV 3-product;
// scale by 1/rowsum in epilogue; output split bf16.
// smem: K[256][72] hi/lo + Vt[64][264] hi/lo + Q[128][72] hi/lo = 178176 B.
// ---------------------------------------------------------------------------
#define KH_B   0
#define KL_B   36864
#define VTH_B  73728
#define VTL_B  107520
#define QH_B   141312
#define QL_B   159744
#define ATT_SMEM 178176
#define KROW   144     // bytes per K/Q row (72 bf16)
#define VROW   528     // bytes per Vt row (264 bf16)

__global__ void __launch_bounds__(256, 1)
attn_tc()
{
    extern __shared__ __nv_bfloat16 smb[];
    const uint32_t sb = smem_u32(smb);
    const int tid  = threadIdx.x;
    const int lane = tid & 31;
    const int wid  = tid >> 5;
    const int n0   = blockIdx.x * 128;
    const int h    = blockIdx.y;
    const int b    = blockIdx.z;
    const int wq   = wid * 16;

    // loads: K rows e (64 bf16 per head slice), Vt rows dv (256 e), Q rows
    {
        const __nv_bfloat16* kh = g_kph + ((size_t)b*E_)*F_ + h*D_;
        const __nv_bfloat16* kl = g_kpl + ((size_t)b*E_)*F_ + h*D_;
        for (int c = tid; c < 2048; c += 256) {
            int e = c >> 3, q = c & 7;
            CP16(sb + KH_B + e*KROW + q*16, kh + (size_t)e*F_ + q*8);
            CP16(sb + KL_B + e*KROW + q*16, kl + (size_t)e*F_ + q*8);
        }
        const __nv_bfloat16* vh = g_vth + ((size_t)b*F_ + h*D_)*E_;
        const __nv_bfloat16* vl = g_vtl + ((size_t)b*F_ + h*D_)*E_;
        for (int c = tid; c < 2048; c += 256) {
            int dv = c >> 5, ch = c & 31;
            CP16(sb + VTH_B + dv*VROW + ch*16, vh + (size_t)dv*E_ + ch*8);
            CP16(sb + VTL_B + dv*VROW + ch*16, vl + (size_t)dv*E_ + ch*8);
        }
        const __nv_bfloat16* qh = g_qh + ((size_t)(b*N_ + n0))*F_ + h*D_;
        const __nv_bfloat16* ql = g_ql + ((size_t)(b*N_ + n0))*F_ + h*D_;
        for (int c = tid; c < 1024; c += 256) {
            int q = c >> 3, k = c & 7;
            CP16(sb + QH_B + q*KROW + k*16, qh + (size_t)q*F_ + k*8);
            CP16(sb + QL_B + q*KROW + k*16, ql + (size_t)q*F_ + k*8);
        }
    }
    CP_COMMIT();
    CP_WAIT0();
    __syncthreads();

    const int lmA = lane & 15;
    const int lkA = (lane >> 4) * 16;
    const int rB  = (lane & 7) + ((lane >> 4) << 3);
    const int lkB = ((lane >> 3) & 1) * 16;

    // ---- scores: 32 n-tiles (e) x m16n8 f32 accumulators ----
    float sc[32][4];
#pragma unroll
    for (int t = 0; t < 32; t++)
#pragma unroll
        for (int v = 0; v < 4; v++) sc[t][v] = 0.f;

#pragma unroll
    for (int kt = 0; kt < 4; kt++) {
        uint32_t qh4[4], ql4[4];
        {
            uint32_t a = sb + QH_B + (wq + lmA) * KROW + lkA + kt * 32;
            ldsm4(qh4, a);
            ldsm4(ql4, a + (QL_B - QH_B));
        }
#pragma unroll
        for (int eb = 0; eb < 16; eb++) {
            uint32_t bh4[4], bl4[4];
            uint32_t a = sb + KH_B + (eb * 16 + rB) * KROW + lkB + kt * 32;
            ldsm4(bh4, a);
            ldsm4(bl4, a + (KL_B - KH_B));
#pragma unroll
            for (int half = 0; half < 2; half++) {
                float* cc = sc[2 * eb + half];
                const uint32_t* bhp = &bh4[half * 2];
                const uint32_t* blp = &bl4[half * 2];
                mma16816(cc, qh4, bhp);
                mma16816(cc, qh4, blp);
                mma16816(cc, ql4, bhp);
            }
        }
    }

    // ---- softmax (unnormalized): rowmax, exp, rowsum ----
    float mx0 = sc[0][0], mx1 = sc[0][2];
#pragma unroll
    for (int t = 0; t < 32; t++) {
        mx0 = fmaxf(mx0, fmaxf(sc[t][0], sc[t][1]));
        mx1 = fmaxf(mx1, fmaxf(sc[t][2], sc[t][3]));
    }
    mx0 = fmaxf(mx0, __shfl_xor_sync(0xffffffffu, mx0, 1));
    mx0 = fmaxf(mx0, __shfl_xor_sync(0xffffffffu, mx0, 2));
    mx1 = fmaxf(mx1, __shfl_xor_sync(0xffffffffu, mx1, 1));
    mx1 = fmaxf(mx1, __shfl_xor_sync(0xffffffffu, mx1, 2));

    float s0 = 0.f, s1 = 0.f;
#pragma unroll
    for (int t = 0; t < 32; t++) {
        sc[t][0] = __expf(sc[t][0] - mx0);
        sc[t][1] = __expf(sc[t][1] - mx0);
        sc[t][2] = __expf(sc[t][2] - mx1);
        sc[t][3] = __expf(sc[t][3] - mx1);
        s0 += sc[t][0] + sc[t][1];
        s1 += sc[t][2] + sc[t][3];
    }
    s0 += __shfl_xor_sync(0xffffffffu, s0, 1);
    s0 += __shfl_xor_sync(0xffffffffu, s0, 2);
    s1 += __shfl_xor_sync(0xffffffffu, s1, 1);
    s1 += __shfl_xor_sync(0xffffffffu, s1, 2);

    // ---- AV: pack P fragments per k-tile, mma against Vt ----
    float o[8][4];
#pragma unroll
    for (int t = 0; t < 8; t++)
#pragma unroll
        for (int v = 0; v < 4; v++) o[t][v] = 0.f;

#pragma unroll
    for (int kt = 0; kt < 16; kt++) {
        uint32_t ph4[4], pl4[4];
        ph4[0] = packbf   (sc[2*kt][0],   sc[2*kt][1]);
        ph4[1] = packbf   (sc[2*kt][2],   sc[2*kt][3]);
        ph4[2] = packbf   (sc[2*kt+1][0], sc[2*kt+1][1]);
        ph4[3] = packbf   (sc[2*kt+1][2], sc[2*kt+1][3]);
        pl4[0] = packbf_lo(sc[2*kt][0],   sc[2*kt][1]);
        pl4[1] = packbf_lo(sc[2*kt][2],   sc[2*kt][3]);
        pl4[2] = packbf_lo(sc[2*kt+1][0], sc[2*kt+1][1]);
        pl4[3] = packbf_lo(sc[2*kt+1][2], sc[2*kt+1][3]);
#pragma unroll
        for (int pr = 0; pr < 4; pr++) {
            uint32_t vh4[4], vl4[4];
            uint32_t a = sb + VTH_B + (pr * 16 + rB) * VROW + lkB + kt * 32;
            ldsm4(vh4, a);
            ldsm4(vl4, a + (VTL_B - VTH_B));
#pragma unroll
            for (int half = 0; half < 2; half++) {
                float* cc = o[2 * pr + half];
                const uint32_t* bhp = &vh4[half * 2];
                const uint32_t* blp = &vl4[half * 2];
                mma16816(cc, ph4, bhp);
                mma16816(cc, ph4, blp);
                mma16816(cc, pl4, bhp);
            }
        }
    }

    // ---- epilogue: normalize by rowsum, split to bf16 hi/lo ----
    const float inv0 = 1.f / s0, inv1 = 1.f / s1;
    const int row0 = b * N_ + n0 + wq + (lane >> 2);
    const int col0 = h * D_ + (lane & 3) * 2;
#pragma unroll
    for (int nt = 0; nt < 8; nt++) {
        float v00 = o[nt][0] * inv0, v01 = o[nt][1] * inv0;
        float v10 = o[nt][2] * inv1, v11 = o[nt][3] * inv1;
        __nv_bfloat16 h0, l0, h1, l1;
        size_t p0 = (size_t)row0 * F_ + col0 + nt * 8;
        split1(v00, h0, l0); split1(v01, h1, l1);
        *(__nv_bfloat162*)&g_aoh[p0] = __nv_bfloat162(h0, h1);
        *(__nv_bfloat162*)&g_aol[p0] = __nv_bfloat162(l0, l1);
        size_t p1 = (size_t)(row0 + 8) * F_ + col0 + nt * 8;
        split1(v10, h0, l0); split1(v11, h1, l1);
        *(__nv_bfloat162*)&g_aoh[p1] = __nv_bfloat162(h0, h1);
        *(__nv_bfloat162*)&g_aol[p1] = __nv_bfloat162(l0, l1);
    }
}

// ---------------------------------------------------------------------------
extern "C" void kernel_launch(void* const* d_in, const int* in_sizes, int n_in,
                              void* d_out, int out_size)
{
    (void)in_sizes; (void)n_in; (void)out_size;
    const float* x    = (const float*)d_in[0];
    const float* proj = (const float*)d_in[1];
    const float* Wq   = (const float*)d_in[2];
    const float* Wk   = (const float*)d_in[3];
    const float* Wv   = (const float*)d_in[4];
    const float* Wo   = (const float*)d_in[5];
    float* out = (float*)d_out;

    __nv_bfloat16 *xh, *xl, *qh, *ql, *aoh, *aol, *xph, *xpl, *ph, *pl;
    __nv_bfloat16 *kph, *kpl, *vth, *vtl;
    __nv_bfloat16 *wqh, *wql, *wkh, *wkl, *wvh, *wvl, *woh, *wol;
    cudaGetSymbolAddress((void**)&xh,  g_xh);
    cudaGetSymbolAddress((void**)&xl,  g_xl);
    cudaGetSymbolAddress((void**)&qh,  g_qh);
    cudaGetSymbolAddress((void**)&ql,  g_ql);
    cudaGetSymbolAddress((void**)&aoh, g_aoh);
    cudaGetSymbolAddress((void**)&aol, g_aol);
    cudaGetSymbolAddress((void**)&xph, g_xph);
    cudaGetSymbolAddress((void**)&xpl, g_xpl);
    cudaGetSymbolAddress((void**)&kph, g_kph);
    cudaGetSymbolAddress((void**)&kpl, g_kpl);
    cudaGetSymbolAddress((void**)&vth, g_vth);
    cudaGetSymbolAddress((void**)&vtl, g_vtl);
    cudaGetSymbolAddress((void**)&ph,  g_ph);
    cudaGetSymbolAddress((void**)&pl,  g_pl);
    cudaGetSymbolAddress((void**)&wqh, g_wqh);
    cudaGetSymbolAddress((void**)&wql, g_wql);
    cudaGetSymbolAddress((void**)&wkh, g_wkh);
    cudaGetSymbolAddress((void**)&wkl, g_wkl);
    cudaGetSymbolAddress((void**)&wvh, g_wvh);
    cudaGetSymbolAddress((void**)&wvl, g_wvl);
    cudaGetSymbolAddress((void**)&woh, g_woh);
    cudaGetSymbolAddress((void**)&wol, g_wol);

    cudaFuncSetAttribute(tc_gemm,
                         cudaFuncAttributeMaxDynamicSharedMemorySize, TCG_SMEM);
    cudaFuncSetAttribute(proj_tc,
                         cudaFuncAttributeMaxDynamicSharedMemorySize, PROJ_SMEM);
    cudaFuncSetAttribute(attn_tc,
                         cudaFuncAttributeMaxDynamicSharedMemorySize, ATT_SMEM);

    // 0) splits
    split_bf16<<<(B_*N_*F_/4 + 255)/256, 256>>>(x,    xh,  xl,  B_*N_*F_/4);
    split_bf16<<<(N_*E_/4   + 255)/256, 256>>>(proj, ph,  pl,  N_*E_/4);
    split_bf16<<<(F_*F_/4   + 255)/256, 256>>>(Wq,   wqh, wql, F_*F_/4);
    split_bf16<<<(F_*F_/4   + 255)/256, 256>>>(Wk,   wkh, wkl, F_*F_/4);
    split_bf16<<<(F_*F_/4   + 255)/256, 256>>>(Wv,   wvh, wvl, F_*F_/4);
    split_bf16<<<(F_*F_/4   + 255)/256, 256>>>(Wo,   woh, wol, F_*F_/4);
    // 1) xp = proj^T @ x (split-K x4) + reduce (emits bf16 hi/lo)
    proj_tc<<<dim3(8, 2, B_ * KSPLIT), 256, PROJ_SMEM>>>(ph, pl, xh, xl);
    xp_reduce<<<(B_*E_*F_/4 + 255)/256, 256>>>();
    // 2) Kp (split bf16) ; Vp (split bf16, transposed to [b][f][e])
    tc_gemm<<<dim3(8, 8, 2), 256, TCG_SMEM>>>(
        xph, xpl, wkh, wkl, wvh, wvl,
        nullptr, nullptr, kph, kpl, vth, vtl, 2, 3, 1.f);
    // 3) Q = 0.125 * x @ Wq^T (split bf16 out)
    tc_gemm<<<dim3(8, 128, 1), 256, TCG_SMEM>>>(
        xh, xl, wqh, wql, wqh, wql,
        nullptr, nullptr, qh, ql, qh, ql, 1, 1, 0.125f);
    // 4) HMMA flash attention -> ao (hi/lo bf16)
    attn_tc<<<dim3(N_ / 128, H_, B_), 256, ATT_SMEM>>>();
    // 5) out = ao @ Wo^T (f32)
    tc_gemm<<<dim3(8, 128, 1), 256, TCG_SMEM>>>(
        aoh, aol, woh, wol, woh, wol,
        out, out, nullptr, nullptr, nullptr, nullptr, 0, 0, 1.f);
}